// round 2
// baseline (speedup 1.0000x reference)
#include <cuda_runtime.h>
#include <math.h>

#define NB     4
#define NPTS   8192
#define NPOINT 409          /* int(8192*0.05) */
#define NG     (NB*NPOINT)  /* 1636 */
#define NSMAX  131

// ---------------- device scratch (no allocations allowed) ----------------
__device__ double g_acc[2];                   // [0]=uniform loss (weighted), [1]=repulsion sum
__device__ float  g_newxyz[NB*NPOINT*3];      // FPS centers
__device__ float  g_grouped[NG*NSMAX*3];      // grouped coords, reused per percentage

__global__ void init_kernel() { g_acc[0] = 0.0; g_acc[1] = 0.0; }

// exact-rounding distance (no FMA contraction): ((dx*dx + dy*dy) + dz*dz)
__device__ __forceinline__ float sqdist_rn(float ax, float ay, float az,
                                           float bx, float by, float bz) {
    float dx = __fadd_rn(ax, -bx);
    float dy = __fadd_rn(ay, -by);
    float dz = __fadd_rn(az, -bz);
    return __fadd_rn(__fadd_rn(__fmul_rn(dx, dx), __fmul_rn(dy, dy)),
                     __fmul_rn(dz, dz));
}

__device__ __forceinline__ float warp_sum(float v) {
    #pragma unroll
    for (int o = 16; o > 0; o >>= 1) v += __shfl_down_sync(0xffffffffu, v, o);
    return v;
}

// =====================  FPS: one block per batch  =====================
__global__ void __launch_bounds__(1024, 1)
fps_kernel(const float* __restrict__ pcd) {
    const int b   = blockIdx.x;
    const int tid = threadIdx.x;
    const float* P = pcd + b * NPTS * 3;
    const int K = NPTS / 1024;  // 8 points per thread, strided

    float px[8], py[8], pz[8], dist[8];
    #pragma unroll
    for (int k = 0; k < K; k++) {
        int j = tid + k * 1024;
        px[k] = P[3*j]; py[k] = P[3*j+1]; pz[k] = P[3*j+2];
        dist[k] = 1e10f;
    }

    __shared__ float sfx, sfy, sfz;
    __shared__ float swv[32];
    __shared__ int   swi[32];
    __shared__ int   s_far;
    if (tid == 0) s_far = 0;
    __syncthreads();

    for (int s = 0; s < NPOINT; s++) {
        if (tid == 0) {
            int far = s_far;
            float fx = P[3*far], fy = P[3*far+1], fz = P[3*far+2];
            sfx = fx; sfy = fy; sfz = fz;
            g_newxyz[(b*NPOINT + s)*3 + 0] = fx;
            g_newxyz[(b*NPOINT + s)*3 + 1] = fy;
            g_newxyz[(b*NPOINT + s)*3 + 2] = fz;
        }
        __syncthreads();
        float fx = sfx, fy = sfy, fz = sfz;

        float bv = -1.0f; int bi = 0x7fffffff;
        #pragma unroll
        for (int k = 0; k < K; k++) {
            float d  = sqdist_rn(px[k], py[k], pz[k], fx, fy, fz);
            float nd = fminf(dist[k], d);
            dist[k]  = nd;
            int j = tid + k * 1024;
            if (nd > bv) { bv = nd; bi = j; }   // k ascending => first max kept
        }
        // warp argmax (tie -> min index, matching jnp.argmax)
        #pragma unroll
        for (int o = 16; o > 0; o >>= 1) {
            float ov = __shfl_down_sync(0xffffffffu, bv, o);
            int   oi = __shfl_down_sync(0xffffffffu, bi, o);
            if (ov > bv || (ov == bv && oi < bi)) { bv = ov; bi = oi; }
        }
        if ((tid & 31) == 0) { swv[tid >> 5] = bv; swi[tid >> 5] = bi; }
        __syncthreads();
        if (tid < 32) {
            bv = swv[tid]; bi = swi[tid];
            #pragma unroll
            for (int o = 16; o > 0; o >>= 1) {
                float ov = __shfl_down_sync(0xffffffffu, bv, o);
                int   oi = __shfl_down_sync(0xffffffffu, bi, o);
                if (ov > bv || (ov == bv && oi < bi)) { bv = ov; bi = oi; }
            }
            if (tid == 0) s_far = bi;
        }
        __syncthreads();
    }
}

// =====================  Repulsion: one thread per query point  =====================
#define RTILE 256

#define INSERT5(dv) do {                                   \
    float _d = (dv);                                       \
    if (_d < s4) { s4 = _d;                                \
        if (s4 < s3) { float _t = s3; s3 = s4; s4 = _t; }  \
        if (s3 < s2) { float _t = s2; s2 = s3; s3 = _t; }  \
        if (s2 < s1) { float _t = s1; s1 = s2; s2 = _t; }  \
        if (s1 < s0) { float _t = s0; s0 = s1; s1 = _t; }  \
    } } while (0)

__global__ void __launch_bounds__(RTILE)
repulsion_kernel(const float* __restrict__ pcd, float r2, float radius, float hh) {
    const int blocks_per_b = NPTS / RTILE;            // 32
    const int b  = blockIdx.x / blocks_per_b;
    const int qi = (blockIdx.x % blocks_per_b) * RTILE + threadIdx.x;
    const float* P = pcd + b * NPTS * 3;

    const float qx = P[3*qi], qy = P[3*qi+1], qz = P[3*qi+2];

    __shared__ float sx[RTILE], sy[RTILE], sz[RTILE];

    float s0 = 1e30f, s1 = 1e30f, s2 = 1e30f, s3 = 1e30f, s4 = 1e30f;
    int   c  = 0;
    float h0 = 0.0f;

    for (int t = 0; t < NPTS; t += RTILE) {
        int j = t + threadIdx.x;
        sx[threadIdx.x] = P[3*j];
        sy[threadIdx.x] = P[3*j+1];
        sz[threadIdx.x] = P[3*j+2];
        __syncthreads();
        #pragma unroll 4
        for (int u = 0; u < RTILE; u++) {
            float d = sqdist_rn(sx[u], sy[u], sz[u], qx, qy, qz);
            if (d <= r2 && c < 20) {          // ballquery: first 20 hits, index order
                if (c == 0) h0 = d;
                c++;
                INSERT5(d);
            }
        }
        __syncthreads();
    }

    // pad with first hit (self always hits so c >= 1); only 5 copies matter
    int pads = 20 - c;
    if (pads > 5) pads = 5;
    for (int k = 0; k < pads; k++) INSERT5(h0);

    // drop smallest (s0); accumulate radius - sqrt(d)*exp(-d/h^2) for ranks 1..4
    float acc = 0.0f;
    {
        float a = s1, bb = s2, cc = s3, dd = s4;
        acc += radius - sqrtf(a)  * expf(-(a  / hh));
        acc += radius - sqrtf(bb) * expf(-(bb / hh));
        acc += radius - sqrtf(cc) * expf(-(cc / hh));
        acc += radius - sqrtf(dd) * expf(-(dd / hh));
    }

    float ws = warp_sum(acc);
    __shared__ float red[RTILE/32];
    if ((threadIdx.x & 31) == 0) red[threadIdx.x >> 5] = ws;
    __syncthreads();
    if (threadIdx.x == 0) {
        float tot = 0.0f;
        #pragma unroll
        for (int w = 0; w < RTILE/32; w++) tot += red[w];
        atomicAdd(&g_acc[1], (double)tot);
    }
}

// ==========  Uniform ballquery + gather: one warp per center  ==========
__global__ void __launch_bounds__(32)
ugroup_kernel(const float* __restrict__ pcd, int ns, float r2) {
    const int g = blockIdx.x;                 // 0..NG-1
    const int b = g / NPOINT;
    const int lane = threadIdx.x;
    const float* P = pcd + b * NPTS * 3;

    const float qx = g_newxyz[g*3], qy = g_newxyz[g*3+1], qz = g_newxyz[g*3+2];
    float* out = g_grouped + (size_t)g * ns * 3;

    int   count = 0;
    float fx0 = 0.f, fy0 = 0.f, fz0 = 0.f;

    for (int t = 0; t < NPTS; t += 32) {
        int j = t + lane;
        float x = P[3*j], y = P[3*j+1], z = P[3*j+2];
        float d = sqdist_rn(x, y, z, qx, qy, qz);
        bool hit = (d <= r2);
        unsigned mask = __ballot_sync(0xffffffffu, hit);
        if (count == 0 && mask) {             // broadcast first hit coords
            int src = __ffs(mask) - 1;
            fx0 = __shfl_sync(0xffffffffu, x, src);
            fy0 = __shfl_sync(0xffffffffu, y, src);
            fz0 = __shfl_sync(0xffffffffu, z, src);
        }
        if (hit) {
            int pos = count + __popc(mask & ((1u << lane) - 1u));
            if (pos < ns) {
                out[pos*3+0] = x; out[pos*3+1] = y; out[pos*3+2] = z;
            }
        }
        count += __popc(mask);
        if (count >= ns) break;
    }
    if (count < ns) {
        for (int sidx = count + lane; sidx < ns; sidx += 32) {
            out[sidx*3+0] = fx0; out[sidx*3+1] = fy0; out[sidx*3+2] = fz0;
        }
    }
}

// ==========  Pairwise 2-smallest within each disk + accumulate  ==========
__global__ void __launch_bounds__(128)
upair_kernel(int ns, float expect_len, float denom, double w) {
    const int g = blockIdx.x;
    const float* grp = g_grouped + (size_t)g * ns * 3;
    __shared__ float sx[NSMAX], sy[NSMAX], sz[NSMAX];
    const int tid = threadIdx.x;

    for (int i = tid; i < ns; i += 128) {
        sx[i] = grp[3*i]; sy[i] = grp[3*i+1]; sz[i] = grp[3*i+2];
    }
    __syncthreads();

    float local = 0.0f;
    for (int i = tid; i < ns; i += 128) {
        float xi = sx[i], yi = sy[i], zi = sz[i];
        float m0 = 1e30f, m1 = 1e30f;
        for (int j = 0; j < ns; j++) {
            float d = sqdist_rn(sx[j], sy[j], sz[j], xi, yi, zi);
            if (d < m0) { m1 = m0; m0 = d; }
            else if (d < m1) { m1 = d; }
        }
        float ud = sqrtf(fabsf(m1 + 1e-8f));  // second-smallest incl. self-zero
        float t  = ud - expect_len;
        local += (t * t) / denom;
    }

    float ws = warp_sum(local);
    __shared__ float red[4];
    if ((tid & 31) == 0) red[tid >> 5] = ws;
    __syncthreads();
    if (tid == 0) {
        float tot = red[0] + red[1] + red[2] + red[3];
        atomicAdd(&g_acc[0], w * (double)tot);
    }
}

__global__ void finalize_kernel(float* out) {
    out[0] = (float)g_acc[0];
    out[1] = (float)(g_acc[1] / (double)(NB * NPTS * 4));
}

// ============================  launch  ============================
extern "C" void kernel_launch(void* const* d_in, const int* in_sizes, int n_in,
                              void* d_out, int out_size) {
    const float* pcd = (const float*)d_in[0];
    float* out = (float*)d_out;

    init_kernel<<<1, 1>>>();
    fps_kernel<<<NB, 1024>>>(pcd);

    {   // repulsion constants (match Python double -> f32 promotion)
        float r2     = (float)(0.07 * 0.07);
        float radius = (float)0.07;
        float hh     = (float)(0.03 * 0.03);
        repulsion_kernel<<<NB * (NPTS / RTILE), RTILE>>>(pcd, r2, radius, hh);
    }

    static const double PS[5] = {0.004, 0.008, 0.01, 0.012, 0.016};
    for (int k = 0; k < 5; k++) {
        double p  = PS[k];
        int    ns = (int)(8192.0 * p);                 // 32, 65, 81, 98, 131
        double r  = sqrt(p * 1.0);
        float  r2 = (float)(r * r);
        double disk = M_PI * 1.0 * p / (double)ns;
        double el   = sqrt(2.0 * disk / 1.732);
        float  elf  = (float)el;
        float  denom = (float)(el + 1e-8);
        double w = (p * 100.0) * (p * 100.0) / ((double)NG * (double)ns) / 5.0;

        ugroup_kernel<<<NG, 32>>>(pcd, ns, r2);
        upair_kernel<<<NG, 128>>>(ns, elf, denom, w);
    }

    finalize_kernel<<<1, 1>>>(out);
}

// round 3
// speedup vs baseline: 1.4915x; 1.4915x over previous
#include <cuda_runtime.h>
#include <math.h>

#define NB     4
#define NPTS   8192
#define NPOINT 409          /* int(8192*0.05) */
#define NG     (NB*NPOINT)  /* 1636 */
#define LTOT   407          /* 32+65+81+98+131 */

// ---------------- device scratch (no allocations allowed) ----------------
__device__ double g_acc[2];                   // [0]=uniform loss (weighted), [1]=repulsion sum
__device__ float  g_newxyz[NB*NPOINT*3];      // FPS centers

__global__ void init_kernel() { g_acc[0] = 0.0; g_acc[1] = 0.0; }

// exact-rounding distance (no FMA contraction): ((dx*dx + dy*dy) + dz*dz)
__device__ __forceinline__ float sqdist_rn(float ax, float ay, float az,
                                           float bx, float by, float bz) {
    float dx = __fadd_rn(ax, -bx);
    float dy = __fadd_rn(ay, -by);
    float dz = __fadd_rn(az, -bz);
    return __fadd_rn(__fadd_rn(__fmul_rn(dx, dx), __fmul_rn(dy, dy)),
                     __fmul_rn(dz, dz));
}

__device__ __forceinline__ float warp_sum(float v) {
    #pragma unroll
    for (int o = 16; o > 0; o >>= 1) v += __shfl_down_sync(0xffffffffu, v, o);
    return v;
}

// =====================  FPS: one block per batch  =====================
__global__ void __launch_bounds__(1024, 1)
fps_kernel(const float* __restrict__ pcd) {
    const int b   = blockIdx.x;
    const int tid = threadIdx.x;
    const float* P = pcd + b * NPTS * 3;
    const int K = NPTS / 1024;  // 8 points per thread, strided

    float px[8], py[8], pz[8], dist[8];
    #pragma unroll
    for (int k = 0; k < K; k++) {
        int j = tid + k * 1024;
        px[k] = P[3*j]; py[k] = P[3*j+1]; pz[k] = P[3*j+2];
        dist[k] = 1e10f;
    }

    __shared__ float sfx, sfy, sfz;
    __shared__ float swv[32];
    __shared__ int   swi[32];
    __shared__ int   s_far;
    if (tid == 0) s_far = 0;
    __syncthreads();

    for (int s = 0; s < NPOINT; s++) {
        if (tid == 0) {
            int far = s_far;
            float fx = P[3*far], fy = P[3*far+1], fz = P[3*far+2];
            sfx = fx; sfy = fy; sfz = fz;
            g_newxyz[(b*NPOINT + s)*3 + 0] = fx;
            g_newxyz[(b*NPOINT + s)*3 + 1] = fy;
            g_newxyz[(b*NPOINT + s)*3 + 2] = fz;
        }
        __syncthreads();
        float fx = sfx, fy = sfy, fz = sfz;

        float bv = -1.0f; int bi = 0x7fffffff;
        #pragma unroll
        for (int k = 0; k < K; k++) {
            float d  = sqdist_rn(px[k], py[k], pz[k], fx, fy, fz);
            float nd = fminf(dist[k], d);
            dist[k]  = nd;
            int j = tid + k * 1024;
            if (nd > bv) { bv = nd; bi = j; }   // k ascending => first max kept
        }
        // warp argmax (tie -> min index, matching jnp.argmax)
        #pragma unroll
        for (int o = 16; o > 0; o >>= 1) {
            float ov = __shfl_down_sync(0xffffffffu, bv, o);
            int   oi = __shfl_down_sync(0xffffffffu, bi, o);
            if (ov > bv || (ov == bv && oi < bi)) { bv = ov; bi = oi; }
        }
        if ((tid & 31) == 0) { swv[tid >> 5] = bv; swi[tid >> 5] = bi; }
        __syncthreads();
        if (tid < 32) {
            bv = swv[tid]; bi = swi[tid];
            #pragma unroll
            for (int o = 16; o > 0; o >>= 1) {
                float ov = __shfl_down_sync(0xffffffffu, bv, o);
                int   oi = __shfl_down_sync(0xffffffffu, bi, o);
                if (ov > bv || (ov == bv && oi < bi)) { bv = ov; bi = oi; }
            }
            if (tid == 0) s_far = bi;
        }
        __syncthreads();
    }
}

// =====================  Repulsion: one thread per query point  =====================
#define RTILE 256

#define INSERT5(dv) do {                                   \
    float _d = (dv);                                       \
    if (_d < s4) { s4 = _d;                                \
        if (s4 < s3) { float _t = s3; s3 = s4; s4 = _t; }  \
        if (s3 < s2) { float _t = s2; s2 = s3; s3 = _t; }  \
        if (s2 < s1) { float _t = s1; s1 = s2; s2 = _t; }  \
        if (s1 < s0) { float _t = s0; s0 = s1; s1 = _t; }  \
    } } while (0)

__global__ void __launch_bounds__(RTILE)
repulsion_kernel(const float* __restrict__ pcd, float r2, float radius, float hh) {
    const int blocks_per_b = NPTS / RTILE;            // 32
    const int b  = blockIdx.x / blocks_per_b;
    const int qi = (blockIdx.x % blocks_per_b) * RTILE + threadIdx.x;
    const float* P = pcd + b * NPTS * 3;

    const float qx = P[3*qi], qy = P[3*qi+1], qz = P[3*qi+2];

    __shared__ float4 sp[RTILE];

    float s0 = 1e30f, s1 = 1e30f, s2 = 1e30f, s3 = 1e30f, s4 = 1e30f;
    int   c  = 0;
    float h0 = 0.0f;

    for (int t = 0; t < NPTS; t += RTILE) {
        int j = t + threadIdx.x;
        sp[threadIdx.x] = make_float4(P[3*j], P[3*j+1], P[3*j+2], 0.0f);
        __syncthreads();
        #pragma unroll 8
        for (int u = 0; u < RTILE; u++) {
            float4 p = sp[u];
            float d = sqdist_rn(p.x, p.y, p.z, qx, qy, qz);
            if (d <= r2 && c < 20) {          // ballquery: first 20 hits, index order
                if (c == 0) h0 = d;
                c++;
                INSERT5(d);
            }
        }
        __syncthreads();
    }

    // pad with first hit (self always hits so c >= 1); only 5 copies matter
    int pads = 20 - c;
    if (pads > 5) pads = 5;
    for (int k = 0; k < pads; k++) INSERT5(h0);

    // drop smallest (s0); accumulate radius - sqrt(d)*exp(-d/h^2) for ranks 1..4
    float acc = 0.0f;
    acc += radius - sqrtf(s1) * expf(-(s1 / hh));
    acc += radius - sqrtf(s2) * expf(-(s2 / hh));
    acc += radius - sqrtf(s3) * expf(-(s3 / hh));
    acc += radius - sqrtf(s4) * expf(-(s4 / hh));

    float ws = warp_sum(acc);
    __shared__ float red[RTILE/32];
    if ((threadIdx.x & 31) == 0) red[threadIdx.x >> 5] = ws;
    __syncthreads();
    if (threadIdx.x == 0) {
        float tot = 0.0f;
        #pragma unroll
        for (int w = 0; w < RTILE/32; w++) tot += red[w];
        atomicAdd(&g_acc[1], (double)tot);
    }
}

// ==========  Fused uniform loss: all 5 levels, one block per center  ==========
struct ULevels {
    float  r2[5];
    float  el[5];
    float  den[5];
    double w[5];
    int    ns[5];
    int    off[5];
};

__global__ void __launch_bounds__(128)
uniform_kernel(const float* __restrict__ pcd, ULevels L) {
    const int g    = blockIdx.x;
    const int b    = g / NPOINT;
    const int tid  = threadIdx.x;
    const int w    = tid >> 5;
    const int lane = tid & 31;
    const float* P = pcd + b * NPTS * 3;

    const float qx = g_newxyz[g*3], qy = g_newxyz[g*3+1], qz = g_newxyz[g*3+2];

    __shared__ float sx[LTOT], sy[LTOT], sz[LTOT];
    __shared__ int   s_cnt[4][5];
    __shared__ int   s_base[4][5];
    __shared__ int   s_u[5];
    __shared__ double s_red[4];

    const int start = w * (NPTS/4);     // 2048 points per warp chunk

    // ---- Pass A: count hits per warp-chunk per level ----
    int cnt0=0,cnt1=0,cnt2=0,cnt3=0,cnt4=0;
    for (int it = 0; it < (NPTS/4)/32; it++) {
        int j = start + it*32 + lane;
        float x = P[3*j], y = P[3*j+1], z = P[3*j+2];
        float d = sqdist_rn(x, y, z, qx, qy, qz);
        cnt0 += __popc(__ballot_sync(0xffffffffu, d <= L.r2[0]));
        cnt1 += __popc(__ballot_sync(0xffffffffu, d <= L.r2[1]));
        cnt2 += __popc(__ballot_sync(0xffffffffu, d <= L.r2[2]));
        cnt3 += __popc(__ballot_sync(0xffffffffu, d <= L.r2[3]));
        cnt4 += __popc(__ballot_sync(0xffffffffu, d <= L.r2[4]));
    }
    if (lane == 0) {
        s_cnt[w][0]=cnt0; s_cnt[w][1]=cnt1; s_cnt[w][2]=cnt2;
        s_cnt[w][3]=cnt3; s_cnt[w][4]=cnt4;
    }
    __syncthreads();
    if (tid < 5) {
        int k = tid, tot = 0;
        #pragma unroll
        for (int ww = 0; ww < 4; ww++) { s_base[ww][k] = tot; tot += s_cnt[ww][k]; }
        s_u[k] = tot < L.ns[k] ? tot : L.ns[k];
    }
    __syncthreads();

    // ---- Pass B: write index-ordered hit lists (first ns per level) ----
    int offs[5];
    #pragma unroll
    for (int k = 0; k < 5; k++) offs[k] = s_base[w][k];
    for (int it = 0; it < (NPTS/4)/32; it++) {
        int j = start + it*32 + lane;
        float x = P[3*j], y = P[3*j+1], z = P[3*j+2];
        float d = sqdist_rn(x, y, z, qx, qy, qz);
        #pragma unroll
        for (int k = 0; k < 5; k++) {
            bool hit = (d <= L.r2[k]);
            unsigned m = __ballot_sync(0xffffffffu, hit);
            if (m && offs[k] < L.ns[k]) {
                if (hit) {
                    int pos = offs[k] + __popc(m & ((1u << lane) - 1u));
                    if (pos < L.ns[k]) {
                        int o = L.off[k] + pos;
                        sx[o] = x; sy[o] = y; sz[o] = z;
                    }
                }
            }
            offs[k] += __popc(m);
        }
    }
    __syncthreads();

    // ---- Pairwise nearest-neighbor per level + weighted accumulation ----
    double acc = 0.0;
    #pragma unroll
    for (int k = 0; k < 5; k++) {
        const int u = s_u[k], ns = L.ns[k], o = L.off[k];
        const float el = L.el[k], den = L.den[k];
        float lsum = 0.0f;
        if (u >= ns) {
            // full list: second-smallest pairwise dist (self dist 0 included)
            for (int j = tid; j < ns; j += 128) {
                float xi = sx[o+j], yi = sy[o+j], zi = sz[o+j];
                float m0 = 1e30f, m1 = 1e30f;
                for (int l = 0; l < ns; l++) {
                    float d = sqdist_rn(sx[o+l], sy[o+l], sz[o+l], xi, yi, zi);
                    if (d < m0) { m1 = m0; m0 = d; }
                    else if (d < m1) { m1 = d; }
                }
                float ud = sqrtf(fabsf(m1 + 1e-8f));
                float t  = ud - el;
                lsum += (t * t) / den;
            }
        } else {
            // padded: first hit + (ns-u) copies -> m1 = 0 for all of them
            if (tid == 0) {
                float ud = sqrtf(1e-8f);
                float t  = ud - el;
                lsum += (float)(ns - u + 1) * ((t * t) / den);
            }
            for (int j = 1 + tid; j < u; j += 128) {
                float xi = sx[o+j], yi = sy[o+j], zi = sz[o+j];
                float m1 = 1e30f;
                for (int l = 0; l < u; l++) {
                    if (l == j) continue;
                    float d = sqdist_rn(sx[o+l], sy[o+l], sz[o+l], xi, yi, zi);
                    m1 = fminf(m1, d);
                }
                float ud = sqrtf(fabsf(m1 + 1e-8f));
                float t  = ud - el;
                lsum += (t * t) / den;
            }
        }
        acc += L.w[k] * (double)lsum;
    }

    // block-reduce the double accumulator
    #pragma unroll
    for (int off = 16; off > 0; off >>= 1)
        acc += __shfl_down_sync(0xffffffffu, acc, off);
    if (lane == 0) s_red[w] = acc;
    __syncthreads();
    if (tid == 0) {
        double tot = s_red[0] + s_red[1] + s_red[2] + s_red[3];
        atomicAdd(&g_acc[0], tot);
    }
}

__global__ void finalize_kernel(float* out) {
    out[0] = (float)g_acc[0];
    out[1] = (float)(g_acc[1] / (double)(NB * NPTS * 4));
}

// ============================  launch  ============================
extern "C" void kernel_launch(void* const* d_in, const int* in_sizes, int n_in,
                              void* d_out, int out_size) {
    const float* pcd = (const float*)d_in[0];
    float* out = (float*)d_out;

    init_kernel<<<1, 1>>>();
    fps_kernel<<<NB, 1024>>>(pcd);

    {   // repulsion constants (match Python double -> f32 promotion)
        float r2     = (float)(0.07 * 0.07);
        float radius = (float)0.07;
        float hh     = (float)(0.03 * 0.03);
        repulsion_kernel<<<NB * (NPTS / RTILE), RTILE>>>(pcd, r2, radius, hh);
    }

    {
        static const double PS[5] = {0.004, 0.008, 0.01, 0.012, 0.016};
        ULevels L;
        int off = 0;
        for (int k = 0; k < 5; k++) {
            double p  = PS[k];
            int    ns = (int)(8192.0 * p);                 // 32, 65, 81, 98, 131
            double r  = sqrt(p * 1.0);
            double disk = M_PI * 1.0 * p / (double)ns;
            double el   = sqrt(2.0 * disk / 1.732);
            L.r2[k]  = (float)(r * r);
            L.el[k]  = (float)el;
            L.den[k] = (float)(el + 1e-8);
            L.w[k]   = (p * 100.0) * (p * 100.0) / ((double)NG * (double)ns) / 5.0;
            L.ns[k]  = ns;
            L.off[k] = off;
            off += ns;
        }
        uniform_kernel<<<NG, 128>>>(pcd, L);
    }

    finalize_kernel<<<1, 1>>>(out);
}

// round 4
// speedup vs baseline: 2.4246x; 1.6255x over previous
#include <cuda_runtime.h>
#include <math.h>

#define NB     4
#define NPTS   8192
#define NPOINT 409          /* int(8192*0.05) */
#define NG     (NB*NPOINT)  /* 1636 */
#define CAP    256          /* stored level-4 hits per center (fast path) */

// ---------------- device scratch (no allocations allowed) ----------------
__device__ double g_acc[2];                   // [0]=uniform loss, [1]=repulsion sum
__device__ float  g_newxyz[NB*NPOINT*3];      // FPS centers

__global__ void init_kernel() { g_acc[0] = 0.0; g_acc[1] = 0.0; }

// exact-rounding distance (FPS only — argmax cascade must match reference)
__device__ __forceinline__ float sqdist_rn(float ax, float ay, float az,
                                           float bx, float by, float bz) {
    float dx = __fadd_rn(ax, -bx);
    float dy = __fadd_rn(ay, -by);
    float dz = __fadd_rn(az, -bz);
    return __fadd_rn(__fadd_rn(__fmul_rn(dx, dx), __fmul_rn(dy, dy)),
                     __fmul_rn(dz, dz));
}
// fast distance (FMA) — continuous-use sites only
__device__ __forceinline__ float sqdist_f(float ax, float ay, float az,
                                          float bx, float by, float bz) {
    float dx = ax - bx, dy = ay - by, dz = az - bz;
    return fmaf(dx, dx, fmaf(dy, dy, dz * dz));
}

__device__ __forceinline__ float warp_sum(float v) {
    #pragma unroll
    for (int o = 16; o > 0; o >>= 1) v += __shfl_down_sync(0xffffffffu, v, o);
    return v;
}

// =====================  FPS: one block per batch  =====================
__global__ void __launch_bounds__(1024, 1)
fps_kernel(const float* __restrict__ pcd) {
    const int b   = blockIdx.x;
    const int tid = threadIdx.x;
    const float* P = pcd + b * NPTS * 3;

    float px[8], py[8], pz[8], dist[8];
    #pragma unroll
    for (int k = 0; k < 8; k++) {
        int j = tid + k * 1024;
        px[k] = P[3*j]; py[k] = P[3*j+1]; pz[k] = P[3*j+2];
        dist[k] = 1e10f;
    }

    __shared__ float sfx, sfy, sfz;
    __shared__ float swv[32];
    __shared__ int   swi[32];

    float fx = P[0], fy = P[1], fz = P[2];      // far_0 = index 0
    if (tid == 0) {
        g_newxyz[b*NPOINT*3 + 0] = fx;
        g_newxyz[b*NPOINT*3 + 1] = fy;
        g_newxyz[b*NPOINT*3 + 2] = fz;
    }

    for (int s = 1; s < NPOINT; s++) {
        // update mins against current far point
        #pragma unroll
        for (int k = 0; k < 8; k++) {
            float d = sqdist_rn(px[k], py[k], pz[k], fx, fy, fz);
            dist[k] = fminf(dist[k], d);
        }
        // per-thread argmax (ascending k => first max kept => smallest index)
        float bv = -1.0f; int bi = 0;
        #pragma unroll
        for (int k = 0; k < 8; k++) {
            if (dist[k] > bv) { bv = dist[k]; bi = tid + k * 1024; }
        }
        // warp argmax (tie -> min index, matching jnp.argmax)
        #pragma unroll
        for (int o = 16; o > 0; o >>= 1) {
            float ov = __shfl_down_sync(0xffffffffu, bv, o);
            int   oi = __shfl_down_sync(0xffffffffu, bi, o);
            if (ov > bv || (ov == bv && oi < bi)) { bv = ov; bi = oi; }
        }
        if ((tid & 31) == 0) { swv[tid >> 5] = bv; swi[tid >> 5] = bi; }
        __syncthreads();
        if (tid < 32) {
            bv = swv[tid]; bi = swi[tid];
            #pragma unroll
            for (int o = 16; o > 0; o >>= 1) {
                float ov = __shfl_down_sync(0xffffffffu, bv, o);
                int   oi = __shfl_down_sync(0xffffffffu, bi, o);
                if (ov > bv || (ov == bv && oi < bi)) { bv = ov; bi = oi; }
            }
            if (tid == 0) {
                float nx = P[3*bi], ny = P[3*bi+1], nz = P[3*bi+2];
                sfx = nx; sfy = ny; sfz = nz;
                g_newxyz[(b*NPOINT + s)*3 + 0] = nx;
                g_newxyz[(b*NPOINT + s)*3 + 1] = ny;
                g_newxyz[(b*NPOINT + s)*3 + 2] = nz;
            }
        }
        __syncthreads();
        fx = sfx; fy = sfy; fz = sfz;
    }
}

// =====================  Repulsion: one thread per query point  =====================
#define RTILE 256

#define INSERT5(dv) do {                                   \
    float _d = (dv);                                       \
    if (_d < s4) { s4 = _d;                                \
        if (s4 < s3) { float _t = s3; s3 = s4; s4 = _t; }  \
        if (s3 < s2) { float _t = s2; s2 = s3; s3 = _t; }  \
        if (s2 < s1) { float _t = s1; s1 = s2; s2 = _t; }  \
        if (s1 < s0) { float _t = s0; s0 = s1; s1 = _t; }  \
    } } while (0)

__global__ void __launch_bounds__(RTILE)
repulsion_kernel(const float* __restrict__ pcd, float r2, float radius, float hh) {
    const int blocks_per_b = NPTS / RTILE;            // 32
    const int b  = blockIdx.x / blocks_per_b;
    const int qi = (blockIdx.x % blocks_per_b) * RTILE + threadIdx.x;
    const float* P = pcd + b * NPTS * 3;

    const float qx = P[3*qi], qy = P[3*qi+1], qz = P[3*qi+2];

    __shared__ float4 sp[RTILE];

    float s0 = 1e30f, s1 = 1e30f, s2 = 1e30f, s3 = 1e30f, s4 = 1e30f;
    int   c  = 0;
    float h0 = 0.0f;

    for (int t = 0; t < NPTS; t += RTILE) {
        int j = t + threadIdx.x;
        sp[threadIdx.x] = make_float4(P[3*j], P[3*j+1], P[3*j+2], 0.0f);
        __syncthreads();
        #pragma unroll 8
        for (int u = 0; u < RTILE; u++) {
            float4 p = sp[u];
            float d = sqdist_f(p.x, p.y, p.z, qx, qy, qz);
            if (d <= r2 && c < 20) {          // ballquery: first 20 hits, index order
                if (c == 0) h0 = d;
                c++;
                INSERT5(d);
            }
        }
        __syncthreads();
    }

    int pads = 20 - c;
    if (pads > 5) pads = 5;
    for (int k = 0; k < pads; k++) INSERT5(h0);

    float acc = 0.0f;
    acc += radius - sqrtf(s1) * expf(-(s1 / hh));
    acc += radius - sqrtf(s2) * expf(-(s2 / hh));
    acc += radius - sqrtf(s3) * expf(-(s3 / hh));
    acc += radius - sqrtf(s4) * expf(-(s4 / hh));

    float ws = warp_sum(acc);
    __shared__ float red[RTILE/32];
    if ((threadIdx.x & 31) == 0) red[threadIdx.x >> 5] = ws;
    __syncthreads();
    if (threadIdx.x == 0) {
        float tot = 0.0f;
        #pragma unroll
        for (int w = 0; w < RTILE/32; w++) tot += red[w];
        atomicAdd(&g_acc[1], (double)tot);
    }
}

// ==========  Uniform loss: one WARP per center, sparse hit storage  ==========
struct ULevels {
    float  r2[5];
    float  el[5];
    float  den[5];
    double w[5];
    int    ns[5];
};

// Evaluate one level from a buffer of stored hits (each float4 = x,y,z,sqdist).
// Entries with h.w <= r2 (in stored order) are the ballquery hit list.
// true_cnt = true number of hits at this radius; list = first min(true_cnt, ns) hits,
// padded to ns with copies of the first hit.
__device__ float eval_level(const float4* H, int n_stored, int true_cnt,
                            float r2, float el, float den, int ns, int lane)
{
    int u = true_cnt < ns ? true_cnt : ns;
    float lsum = 0.0f;
    int jstart = 0;
    if (u < ns) {
        // first hit + (ns-u) copies all have nearest-neighbor dist exactly 0
        if (lane == 0) {
            float ud = sqrtf(1e-8f);
            float t  = ud - el;
            lsum += (float)(ns - u + 1) * ((t * t) / den);
        }
        jstart = 1;
    }
    for (int j = jstart + lane; j < u; j += 32) {
        // locate j-th filtered entry
        float xj = 0.f, yj = 0.f, zj = 0.f;
        int seen = 0;
        for (int i = 0; i < n_stored; i++) {
            float4 h = H[i];
            if (h.w <= r2) {
                if (seen == j) { xj = h.x; yj = h.y; zj = h.z; break; }
                seen++;
            }
        }
        // nearest among the other real entries (first u filtered)
        float m1 = 1e30f;
        seen = 0;
        for (int i = 0; i < n_stored && seen < u; i++) {
            float4 h = H[i];
            if (h.w <= r2) {
                if (seen != j) {
                    float d = sqdist_f(h.x, h.y, h.z, xj, yj, zj);
                    m1 = fminf(m1, d);
                }
                seen++;
            }
        }
        float ud = sqrtf(fabsf(m1 + 1e-8f));
        float t  = ud - el;
        lsum += (t * t) / den;
    }
    return lsum;
}

__global__ void __launch_bounds__(128)
uniform_kernel(const float* __restrict__ pcd, ULevels L) {
    const int wb   = threadIdx.x >> 5;
    const int lane = threadIdx.x & 31;
    const int g    = blockIdx.x * 4 + wb;      // NG = 409*4 exactly
    const int b    = g / NPOINT;
    const float* P = pcd + b * NPTS * 3;

    const float qx = g_newxyz[g*3], qy = g_newxyz[g*3+1], qz = g_newxyz[g*3+2];
    const float r2max = L.r2[4];

    __shared__ float4 sh[4][CAP];
    float4* H = sh[wb];

    // ---- single scan: store all hits at the LARGEST radius (with sqdist) ----
    int cnt4 = 0;
    for (int it = 0; it < NPTS/32; it++) {
        int j = it*32 + lane;
        float x = P[3*j], y = P[3*j+1], z = P[3*j+2];
        float d = sqdist_f(x, y, z, qx, qy, qz);
        bool hit = (d <= r2max);
        unsigned m = __ballot_sync(0xffffffffu, hit);
        if (m) {
            if (hit) {
                int pos = cnt4 + __popc(m & ((1u << lane) - 1u));
                if (pos < CAP) H[pos] = make_float4(x, y, z, d);
            }
            cnt4 += __popc(m);
        }
    }

    double acc = 0.0;
    if (cnt4 <= CAP) {
        // fast path: every level's hit list is a filtered subsequence of H
        #pragma unroll
        for (int k = 0; k < 5; k++) {
            float r2 = L.r2[k];
            int ck = 0;
            for (int i = lane; i < cnt4; i += 32) ck += (H[i].w <= r2) ? 1 : 0;
            #pragma unroll
            for (int o = 16; o > 0; o >>= 1) ck += __shfl_down_sync(0xffffffffu, ck, o);
            ck = __shfl_sync(0xffffffffu, ck, 0);
            float lsum = eval_level(H, cnt4, ck, r2, L.el[k], L.den[k], L.ns[k], lane);
            acc += L.w[k] * (double)lsum;
        }
    } else {
        // overflow fallback (never expected for this data): per-level rescan
        for (int k = 0; k < 5; k++) {
            float r2 = L.r2[k];
            int ns = L.ns[k];
            int c = 0;
            for (int it = 0; it < NPTS/32; it++) {
                int j = it*32 + lane;
                float x = P[3*j], y = P[3*j+1], z = P[3*j+2];
                float d = sqdist_f(x, y, z, qx, qy, qz);
                bool hit = (d <= r2);
                unsigned m = __ballot_sync(0xffffffffu, hit);
                if (hit) {
                    int pos = c + __popc(m & ((1u << lane) - 1u));
                    if (pos < ns) H[pos] = make_float4(x, y, z, d);
                }
                c += __popc(m);
                if (c >= ns) break;
            }
            int stored = c < ns ? c : ns;
            float lsum = eval_level(H, stored, c, r2, L.el[k], L.den[k], ns, lane);
            acc += L.w[k] * (double)lsum;
        }
    }

    // warp-reduce double, one atomic per warp
    #pragma unroll
    for (int o = 16; o > 0; o >>= 1)
        acc += __shfl_down_sync(0xffffffffu, acc, o);
    if (lane == 0) atomicAdd(&g_acc[0], acc);
}

__global__ void finalize_kernel(float* out) {
    out[0] = (float)g_acc[0];
    out[1] = (float)(g_acc[1] / (double)(NB * NPTS * 4));
}

// ============================  launch  ============================
static cudaStream_t g_s2;
static cudaEvent_t  g_ev0, g_ev1;
struct _StreamInit {
    _StreamInit() {
        cudaStreamCreateWithFlags(&g_s2, cudaStreamNonBlocking);
        cudaEventCreateWithFlags(&g_ev0, cudaEventDisableTiming);
        cudaEventCreateWithFlags(&g_ev1, cudaEventDisableTiming);
    }
};
static _StreamInit g_stream_init;

extern "C" void kernel_launch(void* const* d_in, const int* in_sizes, int n_in,
                              void* d_out, int out_size) {
    const float* pcd = (const float*)d_in[0];
    float* out = (float*)d_out;

    init_kernel<<<1, 1>>>();

    // fork: repulsion on side stream, concurrent with FPS + uniform
    cudaEventRecord(g_ev0, 0);
    cudaStreamWaitEvent(g_s2, g_ev0, 0);
    {
        float r2     = (float)(0.07 * 0.07);
        float radius = (float)0.07;
        float hh     = (float)(0.03 * 0.03);
        repulsion_kernel<<<NB * (NPTS / RTILE), RTILE, 0, g_s2>>>(pcd, r2, radius, hh);
    }
    cudaEventRecord(g_ev1, g_s2);

    fps_kernel<<<NB, 1024>>>(pcd);

    {
        static const double PS[5] = {0.004, 0.008, 0.01, 0.012, 0.016};
        ULevels L;
        for (int k = 0; k < 5; k++) {
            double p  = PS[k];
            int    ns = (int)(8192.0 * p);                 // 32, 65, 81, 98, 131
            double r  = sqrt(p * 1.0);
            double disk = M_PI * 1.0 * p / (double)ns;
            double el   = sqrt(2.0 * disk / 1.732);
            L.r2[k]  = (float)(r * r);
            L.el[k]  = (float)el;
            L.den[k] = (float)(el + 1e-8);
            L.w[k]   = (p * 100.0) * (p * 100.0) / ((double)NG * (double)ns) / 5.0;
            L.ns[k]  = ns;
        }
        uniform_kernel<<<NG/4, 128>>>(pcd, L);
    }

    // join: finalize needs both branches
    cudaStreamWaitEvent(0, g_ev1, 0);
    finalize_kernel<<<1, 1>>>(out);
}

// round 5
// speedup vs baseline: 2.6966x; 1.1122x over previous
#include <cuda_runtime.h>
#include <math.h>

#define NB     4
#define NPTS   8192
#define NPOINT 409          /* int(8192*0.05) */
#define NG     (NB*NPOINT)  /* 1636 */
#define CAP    256
#define SEG    64

// ---------------- device scratch (no allocations allowed) ----------------
__device__ double g_acc[2];                   // [0]=uniform, [1]=repulsion sum
__device__ float  g_newxyz[NB*NPOINT*3];      // FPS centers
__device__ float4 g_sorted[NB*NPTS];          // Morton-sorted points (w = orig idx bits)

__global__ void init_kernel() { g_acc[0] = 0.0; g_acc[1] = 0.0; }

// exact-rounding distance (FPS: argmax cascade must match reference exactly)
__device__ __forceinline__ float sqdist_rn(float ax, float ay, float az,
                                           float bx, float by, float bz) {
    float dx = __fadd_rn(ax, -bx);
    float dy = __fadd_rn(ay, -by);
    float dz = __fadd_rn(az, -bz);
    return __fadd_rn(__fadd_rn(__fmul_rn(dx, dx), __fmul_rn(dy, dy)),
                     __fmul_rn(dz, dz));
}
// fast distance (FMA) — continuous-use sites only
__device__ __forceinline__ float sqdist_f(float ax, float ay, float az,
                                          float bx, float by, float bz) {
    float dx = ax - bx, dy = ay - by, dz = az - bz;
    return fmaf(dx, dx, fmaf(dy, dy, dz * dz));
}

__device__ __forceinline__ float warp_sum(float v) {
    #pragma unroll
    for (int o = 16; o > 0; o >>= 1) v += __shfl_down_sync(0xffffffffu, v, o);
    return v;
}

// =====================  Morton sort: one block per batch  =====================
__device__ __forceinline__ unsigned expand10(unsigned v) {
    v &= 1023u;
    v = (v | (v << 16)) & 0x030000FFu;
    v = (v | (v << 8))  & 0x0300F00Fu;
    v = (v | (v << 4))  & 0x030C30C3u;
    v = (v | (v << 2))  & 0x09249249u;
    return v;
}

__global__ void __launch_bounds__(1024, 1)
sort_kernel(const float* __restrict__ pcd) {
    extern __shared__ unsigned long long key[];   // 8192 * 8 = 64 KB
    const int b   = blockIdx.x;
    const int tid = threadIdx.x;
    const float* P = pcd + b * NPTS * 3;

    for (int j = tid; j < NPTS; j += 1024) {
        float x = P[3*j], y = P[3*j+1], z = P[3*j+2];
        unsigned ux = (unsigned)fminf(fmaxf((x + 1.0f) * 512.0f, 0.0f), 1023.0f);
        unsigned uy = (unsigned)fminf(fmaxf((y + 1.0f) * 512.0f, 0.0f), 1023.0f);
        unsigned uz = (unsigned)fminf(fmaxf((z + 1.0f) * 512.0f, 0.0f), 1023.0f);
        unsigned m = expand10(ux) | (expand10(uy) << 1) | (expand10(uz) << 2);
        key[j] = ((unsigned long long)m << 13) | (unsigned)j;
    }
    __syncthreads();

    for (int k = 2; k <= NPTS; k <<= 1) {
        for (int j = k >> 1; j > 0; j >>= 1) {
            for (int i = tid; i < NPTS; i += 1024) {
                int l = i ^ j;
                if (l > i) {
                    unsigned long long a = key[i], c = key[l];
                    bool up = ((i & k) == 0);
                    if ((a > c) == up) { key[i] = c; key[l] = a; }
                }
            }
            __syncthreads();
        }
    }

    for (int j = tid; j < NPTS; j += 1024) {
        int src = (int)(key[j] & 0x1FFFull);
        g_sorted[b*NPTS + j] =
            make_float4(P[3*src], P[3*src+1], P[3*src+2], __int_as_float(src));
    }
}

// ===========  FPS: one block per batch, AABB-pruned warp chunks  ===========
__global__ void __launch_bounds__(1024, 1)
fps_kernel(const float* __restrict__ pcd) {
    const int b    = blockIdx.x;
    const int tid  = threadIdx.x;
    const int w    = tid >> 5;
    const int lane = tid & 31;
    const float4* S = g_sorted + b * NPTS;
    const float*  P = pcd + b * NPTS * 3;

    float px[8], py[8], pz[8], dist[8];
    #pragma unroll
    for (int k = 0; k < 8; k++) {
        int j = w*256 + k*32 + lane;
        float4 f = S[j];
        px[k] = f.x; py[k] = f.y; pz[k] = f.z;
        dist[k] = 1e10f;
    }

    // warp chunk AABB (computed once)
    float lox = px[0], hix = px[0], loy = py[0], hiy = py[0], loz = pz[0], hiz = pz[0];
    #pragma unroll
    for (int k = 1; k < 8; k++) {
        lox = fminf(lox, px[k]); hix = fmaxf(hix, px[k]);
        loy = fminf(loy, py[k]); hiy = fmaxf(hiy, py[k]);
        loz = fminf(loz, pz[k]); hiz = fmaxf(hiz, pz[k]);
    }
    #pragma unroll
    for (int o = 16; o > 0; o >>= 1) {
        lox = fminf(lox, __shfl_xor_sync(0xffffffffu, lox, o));
        hix = fmaxf(hix, __shfl_xor_sync(0xffffffffu, hix, o));
        loy = fminf(loy, __shfl_xor_sync(0xffffffffu, loy, o));
        hiy = fmaxf(hiy, __shfl_xor_sync(0xffffffffu, hiy, o));
        loz = fminf(loz, __shfl_xor_sync(0xffffffffu, loz, o));
        hiz = fmaxf(hiz, __shfl_xor_sync(0xffffffffu, hiz, o));
    }

    float fx = P[0], fy = P[1], fz = P[2];    // far_0 = original index 0
    if (tid == 0) {
        g_newxyz[b*NPOINT*3 + 0] = fx;
        g_newxyz[b*NPOINT*3 + 1] = fy;
        g_newxyz[b*NPOINT*3 + 2] = fz;
    }

    __shared__ unsigned long long skey[2][32];
    unsigned long long wkey = 0;
    float wbv = 1e30f;

    for (int s = 1; s < NPOINT; s++) {
        // lower bound dist(far, warp AABB)^2, deflated for fp safety
        float ax = fmaxf(fmaxf(lox - fx, fx - hix), 0.0f);
        float ay = fmaxf(fmaxf(loy - fy, fy - hiy), 0.0f);
        float az = fmaxf(fmaxf(loz - fz, fz - hiz), 0.0f);
        float lb = (ax*ax + ay*ay + az*az) * 0.999f;

        if (lb < wbv) {
            // exact update + full warp argmax recompute
            float bv = -1.0f; int bi = 0;
            #pragma unroll
            for (int k = 0; k < 8; k++) {
                float d  = sqdist_rn(px[k], py[k], pz[k], fx, fy, fz);
                float nd = fminf(dist[k], d);
                dist[k]  = nd;
                if (nd > bv) { bv = nd; bi = w*256 + k*32 + lane; }
            }
            unsigned long long kk =
                ((unsigned long long)__float_as_uint(bv) << 32) | (unsigned)(8191 - bi);
            #pragma unroll
            for (int o = 16; o > 0; o >>= 1) {
                unsigned long long ok = __shfl_xor_sync(0xffffffffu, kk, o);
                kk = ok > kk ? ok : kk;
            }
            wkey = kk;
            wbv  = __uint_as_float((unsigned)(kk >> 32));
        }
        // (skipped warps: no dist changed, wkey/wbv still valid)

        int p = s & 1;
        if (lane == 0) skey[p][w] = wkey;
        __syncthreads();
        unsigned long long kk = skey[p][lane];
        #pragma unroll
        for (int o = 16; o > 0; o >>= 1) {
            unsigned long long ok = __shfl_xor_sync(0xffffffffu, kk, o);
            kk = ok > kk ? ok : kk;
        }
        int bi = 8191 - (int)(kk & 0xFFFFFFFFull);
        float4 f = S[bi];
        fx = f.x; fy = f.y; fz = f.z;
        if (tid == 0) {
            g_newxyz[(b*NPOINT + s)*3 + 0] = fx;
            g_newxyz[(b*NPOINT + s)*3 + 1] = fy;
            g_newxyz[(b*NPOINT + s)*3 + 2] = fz;
        }
    }
}

// =====================  Repulsion: one thread per query point  =====================
#define RTILE 256

#define INSERT5(dv) do {                                   \
    float _d = (dv);                                       \
    if (_d < s4) { s4 = _d;                                \
        if (s4 < s3) { float _t = s3; s3 = s4; s4 = _t; }  \
        if (s3 < s2) { float _t = s2; s2 = s3; s3 = _t; }  \
        if (s2 < s1) { float _t = s1; s1 = s2; s2 = _t; }  \
        if (s1 < s0) { float _t = s0; s0 = s1; s1 = _t; }  \
    } } while (0)

__global__ void __launch_bounds__(RTILE)
repulsion_kernel(const float* __restrict__ pcd, float r2, float radius, float hh) {
    const int blocks_per_b = NPTS / RTILE;
    const int b  = blockIdx.x / blocks_per_b;
    const int qi = (blockIdx.x % blocks_per_b) * RTILE + threadIdx.x;
    const float* P = pcd + b * NPTS * 3;

    const float qx = P[3*qi], qy = P[3*qi+1], qz = P[3*qi+2];

    __shared__ float4 sp[RTILE];

    float s0 = 1e30f, s1 = 1e30f, s2 = 1e30f, s3 = 1e30f, s4 = 1e30f;
    int   c  = 0;
    float h0 = 0.0f;

    for (int t = 0; t < NPTS; t += RTILE) {
        int j = t + threadIdx.x;
        sp[threadIdx.x] = make_float4(P[3*j], P[3*j+1], P[3*j+2], 0.0f);
        __syncthreads();
        #pragma unroll 8
        for (int u = 0; u < RTILE; u++) {
            float4 p = sp[u];
            float d = sqdist_f(p.x, p.y, p.z, qx, qy, qz);
            if (d <= r2 && c < 20) {
                if (c == 0) h0 = d;
                c++;
                INSERT5(d);
            }
        }
        __syncthreads();
    }

    int pads = 20 - c;
    if (pads > 5) pads = 5;
    for (int k = 0; k < pads; k++) INSERT5(h0);

    float acc = 0.0f;
    acc += radius - sqrtf(s1) * expf(-(s1 / hh));
    acc += radius - sqrtf(s2) * expf(-(s2 / hh));
    acc += radius - sqrtf(s3) * expf(-(s3 / hh));
    acc += radius - sqrtf(s4) * expf(-(s4 / hh));

    float ws = warp_sum(acc);
    __shared__ float red[RTILE/32];
    if ((threadIdx.x & 31) == 0) red[threadIdx.x >> 5] = ws;
    __syncthreads();
    if (threadIdx.x == 0) {
        float tot = 0.0f;
        #pragma unroll
        for (int w = 0; w < RTILE/32; w++) tot += red[w];
        atomicAdd(&g_acc[1], (double)tot);
    }
}

// ==========  Uniform loss: one BLOCK per center, 4-warp split scan  ==========
struct ULevels {
    float  r2[5];
    float  el[5];
    float  den[5];
    double w[5];
    int    ns[5];
};

// H entries: float4 = (x,y,z,sqdist), in ballquery index order.
// Entries with h.w <= r2 form this level's hit list; true_cnt = real hit count;
// list = first min(true_cnt, ns) hits, padded to ns with copies of the first hit.
__device__ float eval_level(const float4* H, int n_stored, int true_cnt,
                            float r2, float el, float den, int ns, int lane)
{
    int u = true_cnt < ns ? true_cnt : ns;
    float lsum = 0.0f;
    int jstart = 0;
    if (u < ns) {
        if (lane == 0) {
            float ud = sqrtf(1e-8f);
            float t  = ud - el;
            lsum += (float)(ns - u + 1) * ((t * t) / den);
        }
        jstart = 1;
    }
    for (int j = jstart + lane; j < u; j += 32) {
        float xj = 0.f, yj = 0.f, zj = 0.f;
        int seen = 0;
        for (int i = 0; i < n_stored; i++) {
            float4 h = H[i];
            if (h.w <= r2) {
                if (seen == j) { xj = h.x; yj = h.y; zj = h.z; break; }
                seen++;
            }
        }
        float m1 = 1e30f;
        seen = 0;
        for (int i = 0; i < n_stored && seen < u; i++) {
            float4 h = H[i];
            if (h.w <= r2) {
                if (seen != j) {
                    float d = sqdist_f(h.x, h.y, h.z, xj, yj, zj);
                    m1 = fminf(m1, d);
                }
                seen++;
            }
        }
        float ud = sqrtf(fabsf(m1 + 1e-8f));
        float t  = ud - el;
        lsum += (t * t) / den;
    }
    return lsum;
}

__global__ void __launch_bounds__(128)
uniform_kernel(const float* __restrict__ pcd, ULevels L) {
    const int g    = blockIdx.x;
    const int b    = g / NPOINT;
    const int tid  = threadIdx.x;
    const int w    = tid >> 5;
    const int lane = tid & 31;
    const float* P = pcd + b * NPTS * 3;

    const float qx = g_newxyz[g*3], qy = g_newxyz[g*3+1], qz = g_newxyz[g*3+2];
    const float r2max = L.r2[4];

    __shared__ float4 Hseg[4*SEG];
    __shared__ float4 H[CAP];
    __shared__ int    s_cnt[4];

    // split scan: warp w covers contiguous index range [w*2048, (w+1)*2048)
    int cnt = 0;
    const int start = w * (NPTS/4);
    for (int it = 0; it < (NPTS/4)/32; it++) {
        int j = start + it*32 + lane;
        float x = P[3*j], y = P[3*j+1], z = P[3*j+2];
        float d = sqdist_f(x, y, z, qx, qy, qz);
        bool hit = (d <= r2max);
        unsigned m = __ballot_sync(0xffffffffu, hit);
        if (m) {
            if (hit) {
                int pos = cnt + __popc(m & ((1u << lane) - 1u));
                if (pos < SEG) Hseg[w*SEG + pos] = make_float4(x, y, z, d);
            }
            cnt += __popc(m);
        }
    }
    if (lane == 0) s_cnt[w] = cnt;
    __syncthreads();

    int c0 = s_cnt[0], c1 = s_cnt[1], c2 = s_cnt[2], c3 = s_cnt[3];
    bool ovf = (c0 > SEG) | (c1 > SEG) | (c2 > SEG) | (c3 > SEG);
    int tot = c0 + c1 + c2 + c3;

    if (!ovf) {
        // concatenate warp segments in index order
        int base = (w > 0 ? c0 : 0) + (w > 1 ? c1 : 0) + (w > 2 ? c2 : 0);
        int mycnt = s_cnt[w];
        for (int i = lane; i < mycnt; i += 32) H[base + i] = Hseg[w*SEG + i];
        __syncthreads();
        if (w == 0) {
            double acc = 0.0;
            #pragma unroll
            for (int k = 0; k < 5; k++) {
                float r2 = L.r2[k];
                int ck = 0;
                for (int i = lane; i < tot; i += 32) ck += (H[i].w <= r2) ? 1 : 0;
                #pragma unroll
                for (int o = 16; o > 0; o >>= 1)
                    ck += __shfl_down_sync(0xffffffffu, ck, o);
                ck = __shfl_sync(0xffffffffu, ck, 0);
                float lsum = eval_level(H, tot, ck, r2, L.el[k], L.den[k], L.ns[k], lane);
                acc += L.w[k] * (double)lsum;
            }
            #pragma unroll
            for (int o = 16; o > 0; o >>= 1)
                acc += __shfl_down_sync(0xffffffffu, acc, o);
            if (lane == 0) atomicAdd(&g_acc[0], acc);
        }
    } else {
        // fallback (never expected): warp-0 per-level ordered rescan
        if (w == 0) {
            double acc = 0.0;
            for (int k = 0; k < 5; k++) {
                float r2 = L.r2[k];
                int ns = L.ns[k];
                int c = 0;
                for (int it = 0; it < NPTS/32; it++) {
                    int j = it*32 + lane;
                    float x = P[3*j], y = P[3*j+1], z = P[3*j+2];
                    float d = sqdist_f(x, y, z, qx, qy, qz);
                    bool hit = (d <= r2);
                    unsigned m = __ballot_sync(0xffffffffu, hit);
                    if (hit) {
                        int pos = c + __popc(m & ((1u << lane) - 1u));
                        if (pos < ns) H[pos] = make_float4(x, y, z, d);
                    }
                    c += __popc(m);
                }
                int stored = c < ns ? c : ns;
                float lsum = eval_level(H, stored, c, r2, L.el[k], L.den[k], ns, lane);
                acc += L.w[k] * (double)lsum;
            }
            #pragma unroll
            for (int o = 16; o > 0; o >>= 1)
                acc += __shfl_down_sync(0xffffffffu, acc, o);
            if (lane == 0) atomicAdd(&g_acc[0], acc);
        }
    }
}

__global__ void finalize_kernel(float* out) {
    out[0] = (float)g_acc[0];
    out[1] = (float)(g_acc[1] / (double)(NB * NPTS * 4));
}

// ============================  launch  ============================
static cudaStream_t g_s2;
static cudaEvent_t  g_ev0, g_ev1;
struct _StreamInit {
    _StreamInit() {
        cudaStreamCreateWithFlags(&g_s2, cudaStreamNonBlocking);
        cudaEventCreateWithFlags(&g_ev0, cudaEventDisableTiming);
        cudaEventCreateWithFlags(&g_ev1, cudaEventDisableTiming);
        cudaFuncSetAttribute(sort_kernel,
                             cudaFuncAttributeMaxDynamicSharedMemorySize, 65536);
    }
};
static _StreamInit g_stream_init;

extern "C" void kernel_launch(void* const* d_in, const int* in_sizes, int n_in,
                              void* d_out, int out_size) {
    const float* pcd = (const float*)d_in[0];
    float* out = (float*)d_out;

    init_kernel<<<1, 1>>>();

    // fork: repulsion on side stream, concurrent with sort+FPS+uniform
    cudaEventRecord(g_ev0, 0);
    cudaStreamWaitEvent(g_s2, g_ev0, 0);
    {
        float r2     = (float)(0.07 * 0.07);
        float radius = (float)0.07;
        float hh     = (float)(0.03 * 0.03);
        repulsion_kernel<<<NB * (NPTS / RTILE), RTILE, 0, g_s2>>>(pcd, r2, radius, hh);
    }
    cudaEventRecord(g_ev1, g_s2);

    sort_kernel<<<NB, 1024, 65536>>>(pcd);
    fps_kernel<<<NB, 1024>>>(pcd);

    {
        static const double PS[5] = {0.004, 0.008, 0.01, 0.012, 0.016};
        ULevels L;
        for (int k = 0; k < 5; k++) {
            double p  = PS[k];
            int    ns = (int)(8192.0 * p);
            double r  = sqrt(p * 1.0);
            double disk = M_PI * 1.0 * p / (double)ns;
            double el   = sqrt(2.0 * disk / 1.732);
            L.r2[k]  = (float)(r * r);
            L.el[k]  = (float)el;
            L.den[k] = (float)(el + 1e-8);
            L.w[k]   = (p * 100.0) * (p * 100.0) / ((double)NG * (double)ns) / 5.0;
            L.ns[k]  = ns;
        }
        uniform_kernel<<<NG, 128>>>(pcd, L);
    }

    cudaStreamWaitEvent(0, g_ev1, 0);
    finalize_kernel<<<1, 1>>>(out);
}

// round 6
// speedup vs baseline: 2.8562x; 1.0592x over previous
#include <cuda_runtime.h>
#include <math.h>

#define NB     4
#define NPTS   8192
#define NPOINT 409          /* int(8192*0.05) */
#define NG     (NB*NPOINT)  /* 1636 */
#define CAP    256
#define SEG    64

// ---------------- device scratch (no allocations allowed) ----------------
__device__ double g_acc[2];                   // [0]=uniform, [1]=repulsion sum
__device__ float  g_newxyz[NB*NPOINT*3];      // FPS centers
__device__ float4 g_sorted[NB*NPTS];          // Morton-sorted points (w = orig idx)

__global__ void init_kernel() { g_acc[0] = 0.0; g_acc[1] = 0.0; }

// exact-rounding distance (FPS argmax must match reference exactly)
__device__ __forceinline__ float sqdist_rn(float ax, float ay, float az,
                                           float bx, float by, float bz) {
    float dx = __fadd_rn(ax, -bx);
    float dy = __fadd_rn(ay, -by);
    float dz = __fadd_rn(az, -bz);
    return __fadd_rn(__fadd_rn(__fmul_rn(dx, dx), __fmul_rn(dy, dy)),
                     __fmul_rn(dz, dz));
}
// fast distance (FMA) — continuous-use sites only
__device__ __forceinline__ float sqdist_f(float ax, float ay, float az,
                                          float bx, float by, float bz) {
    float dx = ax - bx, dy = ay - by, dz = az - bz;
    return fmaf(dx, dx, fmaf(dy, dy, dz * dz));
}

__device__ __forceinline__ float warp_sum(float v) {
    #pragma unroll
    for (int o = 16; o > 0; o >>= 1) v += __shfl_down_sync(0xffffffffu, v, o);
    return v;
}

// ---- packed f32x2 helpers (per-lane IEEE .rn — bit-exact vs scalar) ----
__device__ __forceinline__ unsigned long long pack2(float lo, float hi) {
    unsigned long long r;
    asm("mov.b64 %0, {%1, %2};" : "=l"(r) : "f"(lo), "f"(hi));
    return r;
}
__device__ __forceinline__ void unpack2(unsigned long long v, float& lo, float& hi) {
    asm("mov.b64 {%0, %1}, %2;" : "=f"(lo), "=f"(hi) : "l"(v));
}
__device__ __forceinline__ unsigned long long add2(unsigned long long a,
                                                   unsigned long long b) {
    unsigned long long r;
    asm("add.rn.f32x2 %0, %1, %2;" : "=l"(r) : "l"(a), "l"(b));
    return r;
}
__device__ __forceinline__ unsigned long long mul2(unsigned long long a,
                                                   unsigned long long b) {
    unsigned long long r;
    asm("mul.rn.f32x2 %0, %1, %2;" : "=l"(r) : "l"(a), "l"(b));
    return r;
}

// =====================  Morton sort (u32 keys): one block per batch  =====================
__device__ __forceinline__ unsigned expandb(unsigned v) {
    v &= 1023u;
    v = (v | (v << 16)) & 0x030000FFu;
    v = (v | (v << 8))  & 0x0300F00Fu;
    v = (v | (v << 4))  & 0x030C30C3u;
    v = (v | (v << 2))  & 0x09249249u;
    return v;
}

__global__ void __launch_bounds__(1024, 1)
sort_kernel(const float* __restrict__ pcd) {
    __shared__ unsigned key[NPTS];                // 32 KB
    const int b   = blockIdx.x;
    const int tid = threadIdx.x;
    const float* P = pcd + b * NPTS * 3;

    for (int j = tid; j < NPTS; j += 1024) {
        float x = P[3*j], y = P[3*j+1], z = P[3*j+2];
        unsigned ux = (unsigned)fminf(fmaxf((x + 1.0f) * 32.0f, 0.0f), 63.0f);
        unsigned uy = (unsigned)fminf(fmaxf((y + 1.0f) * 32.0f, 0.0f), 63.0f);
        unsigned uz = (unsigned)fminf(fmaxf((z + 1.0f) * 32.0f, 0.0f), 63.0f);
        unsigned m = expandb(ux) | (expandb(uy) << 1) | (expandb(uz) << 2); // 18 bits
        key[j] = (m << 13) | (unsigned)j;
    }
    __syncthreads();

    for (int k = 2; k <= NPTS; k <<= 1) {
        for (int j = k >> 1; j > 0; j >>= 1) {
            for (int i = tid; i < NPTS; i += 1024) {
                int l = i ^ j;
                if (l > i) {
                    unsigned a = key[i], c = key[l];
                    bool up = ((i & k) == 0);
                    if ((a > c) == up) { key[i] = c; key[l] = a; }
                }
            }
            __syncthreads();
        }
    }

    for (int j = tid; j < NPTS; j += 1024) {
        int src = (int)(key[j] & 0x1FFFu);
        g_sorted[b*NPTS + j] =
            make_float4(P[3*src], P[3*src+1], P[3*src+2], __int_as_float(src));
    }
}

// ===========  FPS: lane-granular AABB pruning + packed exact update  ===========
__global__ void __launch_bounds__(1024, 1)
fps_kernel(const float* __restrict__ pcd) {
    const int b    = blockIdx.x;
    const int tid  = threadIdx.x;
    const int lane = tid & 31;
    const float4* S = g_sorted + b * NPTS;
    const float*  P = pcd + b * NPTS * 3;

    // lane owns 8 CONTIGUOUS sorted points [tid*8, tid*8+8)
    unsigned long long px2[4], py2[4], pz2[4];
    int   oidp[4];                      // packed orig idx pairs (hi<<16|lo)
    float dist[8];
    float lox, hix, loy, hiy, loz, hiz;
    {
        float xs[8], ys[8], zs[8];
        #pragma unroll
        for (int k = 0; k < 8; k++) {
            float4 f = S[tid*8 + k];
            xs[k] = f.x; ys[k] = f.y; zs[k] = f.z;
            dist[k] = 1e10f;
            int oi = __float_as_int(f.w);
            if (k & 1) oidp[k>>1] |= oi << 16; else oidp[k>>1] = oi;
        }
        #pragma unroll
        for (int i = 0; i < 4; i++) {
            px2[i] = pack2(xs[2*i], xs[2*i+1]);
            py2[i] = pack2(ys[2*i], ys[2*i+1]);
            pz2[i] = pack2(zs[2*i], zs[2*i+1]);
        }
        lox = xs[0]; hix = xs[0]; loy = ys[0]; hiy = ys[0]; loz = zs[0]; hiz = zs[0];
        #pragma unroll
        for (int k = 1; k < 8; k++) {
            lox = fminf(lox, xs[k]); hix = fmaxf(hix, xs[k]);
            loy = fminf(loy, ys[k]); hiy = fmaxf(hiy, ys[k]);
            loz = fminf(loz, zs[k]); hiz = fmaxf(hiz, zs[k]);
        }
    }

    __shared__ unsigned long long slot[3];
    if (tid < 3) slot[tid] = 0ull;

    float dmax = 1e10f;
    unsigned long long lkey = 0ull, wkey = 0ull;

    float fx = P[0], fy = P[1], fz = P[2];       // far_0 = original index 0
    if (tid == 0) {
        g_newxyz[b*NPOINT*3 + 0] = fx;
        g_newxyz[b*NPOINT*3 + 1] = fy;
        g_newxyz[b*NPOINT*3 + 2] = fz;
    }
    __syncthreads();

    for (int s = 1; s < NPOINT; s++) {
        // lane lower-bound to its AABB, deflated for fp safety
        float ax = fmaxf(fmaxf(lox - fx, fx - hix), 0.0f);
        float ay = fmaxf(fmaxf(loy - fy, fy - hiy), 0.0f);
        float az = fmaxf(fmaxf(loz - fz, fz - hiz), 0.0f);
        float lb = (ax*ax + ay*ay + az*az) * 0.999f;
        bool active = lb < dmax;
        unsigned am = __ballot_sync(0xffffffffu, active);

        if (am) {
            if (active) {
                unsigned long long nfx = pack2(-fx, -fx);
                unsigned long long nfy = pack2(-fy, -fy);
                unsigned long long nfz = pack2(-fz, -fz);
                #pragma unroll
                for (int i = 0; i < 4; i++) {
                    unsigned long long dx = add2(px2[i], nfx);
                    unsigned long long dy = add2(py2[i], nfy);
                    unsigned long long dz = add2(pz2[i], nfz);
                    unsigned long long d2 =
                        add2(add2(mul2(dx, dx), mul2(dy, dy)), mul2(dz, dz));
                    float d0, d1; unpack2(d2, d0, d1);
                    dist[2*i]   = fminf(dist[2*i],   d0);
                    dist[2*i+1] = fminf(dist[2*i+1], d1);
                }
                // lane argmax over 8 (tie -> smaller ORIGINAL index)
                float bv = -1.0f; int bi = 0x7fffffff;
                #pragma unroll
                for (int k = 0; k < 8; k++) {
                    int oi = (oidp[k>>1] >> ((k & 1) * 16)) & 0xFFFF;
                    if (dist[k] > bv || (dist[k] == bv && oi < bi)) {
                        bv = dist[k]; bi = oi;
                    }
                }
                dmax = bv;
                lkey = ((unsigned long long)__float_as_uint(bv) << 32)
                       | (unsigned)(8191 - bi);
            }
            // warp reduce over cached/updated lane keys
            unsigned long long kk = lkey;
            #pragma unroll
            for (int o = 16; o > 0; o >>= 1) {
                unsigned long long ok = __shfl_xor_sync(0xffffffffu, kk, o);
                kk = ok > kk ? ok : kk;
            }
            wkey = kk;
        }
        if (lane == 0) atomicMax(&slot[s % 3], wkey);
        __syncthreads();
        unsigned long long r = slot[s % 3];
        if (tid == 0) slot[(s + 2) % 3] = 0ull;   // reused at iter s+2; bar s+1 orders
        int oi = 8191 - (int)(r & 0xFFFFFFFFull);
        fx = __ldg(&P[3*oi]); fy = __ldg(&P[3*oi+1]); fz = __ldg(&P[3*oi+2]);
        if (tid == 0) {
            g_newxyz[(b*NPOINT + s)*3 + 0] = fx;
            g_newxyz[(b*NPOINT + s)*3 + 1] = fy;
            g_newxyz[(b*NPOINT + s)*3 + 2] = fz;
        }
    }
}

// =====================  Repulsion: one thread per query point  =====================
#define RTILE 256

#define INSERT5(dv) do {                                   \
    float _d = (dv);                                       \
    if (_d < s4) { s4 = _d;                                \
        if (s4 < s3) { float _t = s3; s3 = s4; s4 = _t; }  \
        if (s3 < s2) { float _t = s2; s2 = s3; s3 = _t; }  \
        if (s2 < s1) { float _t = s1; s1 = s2; s2 = _t; }  \
        if (s1 < s0) { float _t = s0; s0 = s1; s1 = _t; }  \
    } } while (0)

__global__ void __launch_bounds__(RTILE)
repulsion_kernel(const float* __restrict__ pcd, float r2, float radius, float hh) {
    const int blocks_per_b = NPTS / RTILE;
    const int b  = blockIdx.x / blocks_per_b;
    const int qi = (blockIdx.x % blocks_per_b) * RTILE + threadIdx.x;
    const float* P = pcd + b * NPTS * 3;

    const float qx = P[3*qi], qy = P[3*qi+1], qz = P[3*qi+2];

    __shared__ float4 sp[RTILE];

    float s0 = 1e30f, s1 = 1e30f, s2 = 1e30f, s3 = 1e30f, s4 = 1e30f;
    int   c  = 0;
    float h0 = 0.0f;

    for (int t = 0; t < NPTS; t += RTILE) {
        int j = t + threadIdx.x;
        sp[threadIdx.x] = make_float4(P[3*j], P[3*j+1], P[3*j+2], 0.0f);
        __syncthreads();
        #pragma unroll 8
        for (int u = 0; u < RTILE; u++) {
            float4 p = sp[u];
            float d = sqdist_f(p.x, p.y, p.z, qx, qy, qz);
            if (d <= r2 && c < 20) {
                if (c == 0) h0 = d;
                c++;
                INSERT5(d);
            }
        }
        __syncthreads();
    }

    int pads = 20 - c;
    if (pads > 5) pads = 5;
    for (int k = 0; k < pads; k++) INSERT5(h0);

    float acc = 0.0f;
    acc += radius - sqrtf(s1) * expf(-(s1 / hh));
    acc += radius - sqrtf(s2) * expf(-(s2 / hh));
    acc += radius - sqrtf(s3) * expf(-(s3 / hh));
    acc += radius - sqrtf(s4) * expf(-(s4 / hh));

    float ws = warp_sum(acc);
    __shared__ float red[RTILE/32];
    if ((threadIdx.x & 31) == 0) red[threadIdx.x >> 5] = ws;
    __syncthreads();
    if (threadIdx.x == 0) {
        float tot = 0.0f;
        #pragma unroll
        for (int w = 0; w < RTILE/32; w++) tot += red[w];
        atomicAdd(&g_acc[1], (double)tot);
    }
}

// ==========  Uniform loss: one BLOCK per center, 4-warp split scan  ==========
struct ULevels {
    float  r2[5];
    float  el[5];
    float  den[5];
    double w[5];
    int    ns[5];
};

__device__ float eval_level(const float4* H, int n_stored, int true_cnt,
                            float r2, float el, float den, int ns, int lane)
{
    int u = true_cnt < ns ? true_cnt : ns;
    float lsum = 0.0f;
    int jstart = 0;
    if (u < ns) {
        if (lane == 0) {
            float ud = sqrtf(1e-8f);
            float t  = ud - el;
            lsum += (float)(ns - u + 1) * ((t * t) / den);
        }
        jstart = 1;
    }
    for (int j = jstart + lane; j < u; j += 32) {
        float xj = 0.f, yj = 0.f, zj = 0.f;
        int seen = 0;
        for (int i = 0; i < n_stored; i++) {
            float4 h = H[i];
            if (h.w <= r2) {
                if (seen == j) { xj = h.x; yj = h.y; zj = h.z; break; }
                seen++;
            }
        }
        float m1 = 1e30f;
        seen = 0;
        for (int i = 0; i < n_stored && seen < u; i++) {
            float4 h = H[i];
            if (h.w <= r2) {
                if (seen != j) {
                    float d = sqdist_f(h.x, h.y, h.z, xj, yj, zj);
                    m1 = fminf(m1, d);
                }
                seen++;
            }
        }
        float ud = sqrtf(fabsf(m1 + 1e-8f));
        float t  = ud - el;
        lsum += (t * t) / den;
    }
    return lsum;
}

__global__ void __launch_bounds__(128)
uniform_kernel(const float* __restrict__ pcd, ULevels L) {
    const int g    = blockIdx.x;
    const int b    = g / NPOINT;
    const int tid  = threadIdx.x;
    const int w    = tid >> 5;
    const int lane = tid & 31;
    const float* P = pcd + b * NPTS * 3;

    const float qx = g_newxyz[g*3], qy = g_newxyz[g*3+1], qz = g_newxyz[g*3+2];
    const float r2max = L.r2[4];

    __shared__ float4 Hseg[4*SEG];
    __shared__ float4 H[CAP];
    __shared__ int    s_cnt[4];

    int cnt = 0;
    const int start = w * (NPTS/4);
    for (int it = 0; it < (NPTS/4)/32; it++) {
        int j = start + it*32 + lane;
        float x = __ldg(&P[3*j]), y = __ldg(&P[3*j+1]), z = __ldg(&P[3*j+2]);
        float d = sqdist_f(x, y, z, qx, qy, qz);
        bool hit = (d <= r2max);
        unsigned m = __ballot_sync(0xffffffffu, hit);
        if (m) {
            if (hit) {
                int pos = cnt + __popc(m & ((1u << lane) - 1u));
                if (pos < SEG) Hseg[w*SEG + pos] = make_float4(x, y, z, d);
            }
            cnt += __popc(m);
        }
    }
    if (lane == 0) s_cnt[w] = cnt;
    __syncthreads();

    int c0 = s_cnt[0], c1 = s_cnt[1], c2 = s_cnt[2], c3 = s_cnt[3];
    bool ovf = (c0 > SEG) | (c1 > SEG) | (c2 > SEG) | (c3 > SEG);
    int tot = c0 + c1 + c2 + c3;

    if (!ovf) {
        int base = (w > 0 ? c0 : 0) + (w > 1 ? c1 : 0) + (w > 2 ? c2 : 0);
        int mycnt = s_cnt[w];
        for (int i = lane; i < mycnt; i += 32) H[base + i] = Hseg[w*SEG + i];
        __syncthreads();
        if (w == 0) {
            double acc = 0.0;
            #pragma unroll
            for (int k = 0; k < 5; k++) {
                float r2 = L.r2[k];
                int ck = 0;
                for (int i = lane; i < tot; i += 32) ck += (H[i].w <= r2) ? 1 : 0;
                #pragma unroll
                for (int o = 16; o > 0; o >>= 1)
                    ck += __shfl_down_sync(0xffffffffu, ck, o);
                ck = __shfl_sync(0xffffffffu, ck, 0);
                float lsum = eval_level(H, tot, ck, r2, L.el[k], L.den[k], L.ns[k], lane);
                acc += L.w[k] * (double)lsum;
            }
            #pragma unroll
            for (int o = 16; o > 0; o >>= 1)
                acc += __shfl_down_sync(0xffffffffu, acc, o);
            if (lane == 0) atomicAdd(&g_acc[0], acc);
        }
    } else {
        if (w == 0) {
            double acc = 0.0;
            for (int k = 0; k < 5; k++) {
                float r2 = L.r2[k];
                int ns = L.ns[k];
                int c = 0;
                for (int it = 0; it < NPTS/32; it++) {
                    int j = it*32 + lane;
                    float x = P[3*j], y = P[3*j+1], z = P[3*j+2];
                    float d = sqdist_f(x, y, z, qx, qy, qz);
                    bool hit = (d <= r2);
                    unsigned m = __ballot_sync(0xffffffffu, hit);
                    if (hit) {
                        int pos = c + __popc(m & ((1u << lane) - 1u));
                        if (pos < ns) H[pos] = make_float4(x, y, z, d);
                    }
                    c += __popc(m);
                }
                int stored = c < ns ? c : ns;
                float lsum = eval_level(H, stored, c, r2, L.el[k], L.den[k], ns, lane);
                acc += L.w[k] * (double)lsum;
            }
            #pragma unroll
            for (int o = 16; o > 0; o >>= 1)
                acc += __shfl_down_sync(0xffffffffu, acc, o);
            if (lane == 0) atomicAdd(&g_acc[0], acc);
        }
    }
}

__global__ void finalize_kernel(float* out) {
    out[0] = (float)g_acc[0];
    out[1] = (float)(g_acc[1] / (double)(NB * NPTS * 4));
}

// ============================  launch  ============================
static cudaStream_t g_s2;
static cudaEvent_t  g_ev0, g_ev1;
struct _StreamInit {
    _StreamInit() {
        cudaStreamCreateWithFlags(&g_s2, cudaStreamNonBlocking);
        cudaEventCreateWithFlags(&g_ev0, cudaEventDisableTiming);
        cudaEventCreateWithFlags(&g_ev1, cudaEventDisableTiming);
    }
};
static _StreamInit g_stream_init;

extern "C" void kernel_launch(void* const* d_in, const int* in_sizes, int n_in,
                              void* d_out, int out_size) {
    const float* pcd = (const float*)d_in[0];
    float* out = (float*)d_out;

    init_kernel<<<1, 1>>>();

    // fork: repulsion on side stream, concurrent with sort+FPS+uniform
    cudaEventRecord(g_ev0, 0);
    cudaStreamWaitEvent(g_s2, g_ev0, 0);
    {
        float r2     = (float)(0.07 * 0.07);
        float radius = (float)0.07;
        float hh     = (float)(0.03 * 0.03);
        repulsion_kernel<<<NB * (NPTS / RTILE), RTILE, 0, g_s2>>>(pcd, r2, radius, hh);
    }
    cudaEventRecord(g_ev1, g_s2);

    sort_kernel<<<NB, 1024>>>(pcd);
    fps_kernel<<<NB, 1024>>>(pcd);

    {
        static const double PS[5] = {0.004, 0.008, 0.01, 0.012, 0.016};
        ULevels L;
        for (int k = 0; k < 5; k++) {
            double p  = PS[k];
            int    ns = (int)(8192.0 * p);
            double r  = sqrt(p * 1.0);
            double disk = M_PI * 1.0 * p / (double)ns;
            double el   = sqrt(2.0 * disk / 1.732);
            L.r2[k]  = (float)(r * r);
            L.el[k]  = (float)el;
            L.den[k] = (float)(el + 1e-8);
            L.w[k]   = (p * 100.0) * (p * 100.0) / ((double)NG * (double)ns) / 5.0;
            L.ns[k]  = ns;
        }
        uniform_kernel<<<NG, 128>>>(pcd, L);
    }

    cudaStreamWaitEvent(0, g_ev1, 0);
    finalize_kernel<<<1, 1>>>(out);
}

// round 7
// speedup vs baseline: 3.0589x; 1.0709x over previous
#include <cuda_runtime.h>
#include <math.h>

#define NB     4
#define NPTS   8192
#define NPOINT 409          /* int(8192*0.05) */
#define NG     (NB*NPOINT)  /* 1636 */
#define CAP    256
#define SEG    64

// ---------------- device scratch (no allocations allowed) ----------------
__device__ double g_acc[2];                   // [0]=uniform, [1]=repulsion sum
__device__ float  g_newxyz[NB*NPOINT*3];      // FPS centers
__device__ float4 g_sorted[NB*NPTS];          // Morton-sorted points (w = orig idx)

__global__ void init_kernel() { g_acc[0] = 0.0; g_acc[1] = 0.0; }

// exact-rounding distance (FPS argmax must match reference exactly)
__device__ __forceinline__ float sqdist_rn(float ax, float ay, float az,
                                           float bx, float by, float bz) {
    float dx = __fadd_rn(ax, -bx);
    float dy = __fadd_rn(ay, -by);
    float dz = __fadd_rn(az, -bz);
    return __fadd_rn(__fadd_rn(__fmul_rn(dx, dx), __fmul_rn(dy, dy)),
                     __fmul_rn(dz, dz));
}
// fast distance (FMA) — continuous-use sites only
__device__ __forceinline__ float sqdist_f(float ax, float ay, float az,
                                          float bx, float by, float bz) {
    float dx = ax - bx, dy = ay - by, dz = az - bz;
    return fmaf(dx, dx, fmaf(dy, dy, dz * dz));
}

__device__ __forceinline__ float warp_sum(float v) {
    #pragma unroll
    for (int o = 16; o > 0; o >>= 1) v += __shfl_down_sync(0xffffffffu, v, o);
    return v;
}

// =====================  Morton sort (u32 keys): one block per batch  =====================
__device__ __forceinline__ unsigned expandb(unsigned v) {
    v &= 1023u;
    v = (v | (v << 16)) & 0x030000FFu;
    v = (v | (v << 8))  & 0x0300F00Fu;
    v = (v | (v << 4))  & 0x030C30C3u;
    v = (v | (v << 2))  & 0x09249249u;
    return v;
}

__global__ void __launch_bounds__(1024, 1)
sort_kernel(const float* __restrict__ pcd) {
    __shared__ unsigned key[NPTS];                // 32 KB
    const int b   = blockIdx.x;
    const int tid = threadIdx.x;
    const float* P = pcd + b * NPTS * 3;

    for (int j = tid; j < NPTS; j += 1024) {
        float x = P[3*j], y = P[3*j+1], z = P[3*j+2];
        unsigned ux = (unsigned)fminf(fmaxf((x + 1.0f) * 32.0f, 0.0f), 63.0f);
        unsigned uy = (unsigned)fminf(fmaxf((y + 1.0f) * 32.0f, 0.0f), 63.0f);
        unsigned uz = (unsigned)fminf(fmaxf((z + 1.0f) * 32.0f, 0.0f), 63.0f);
        unsigned m = expandb(ux) | (expandb(uy) << 1) | (expandb(uz) << 2); // 18 bits
        key[j] = (m << 13) | (unsigned)j;
    }
    __syncthreads();

    for (int k = 2; k <= NPTS; k <<= 1) {
        for (int j = k >> 1; j > 0; j >>= 1) {
            for (int i = tid; i < NPTS; i += 1024) {
                int l = i ^ j;
                if (l > i) {
                    unsigned a = key[i], c = key[l];
                    bool up = ((i & k) == 0);
                    if ((a > c) == up) { key[i] = c; key[l] = a; }
                }
            }
            __syncthreads();
        }
    }

    for (int j = tid; j < NPTS; j += 1024) {
        int src = (int)(key[j] & 0x1FFFu);
        g_sorted[b*NPTS + j] =
            make_float4(P[3*src], P[3*src+1], P[3*src+2], __int_as_float(src));
    }
}

// ===========  FPS: warp-granular AABB prune, smem far-fetch, redux argmax  ===========
__global__ void __launch_bounds__(1024, 1)
fps_kernel(const float* __restrict__ pcd) {
    extern __shared__ float ctab[];               // cx[8192] cy[8192] cz[8192]
    float* cx = ctab;
    float* cy = ctab + NPTS;
    float* cz = ctab + 2*NPTS;

    const int b    = blockIdx.x;
    const int tid  = threadIdx.x;
    const int w    = tid >> 5;
    const int lane = tid & 31;
    const float4* S = g_sorted + b * NPTS;
    const float*  P = pcd + b * NPTS * 3;

    // coordinate table indexed by ORIGINAL index (far-point fetch = LDS)
    for (int j = tid; j < NPTS; j += 1024) {
        cx[j] = P[3*j]; cy[j] = P[3*j+1]; cz[j] = P[3*j+2];
    }

    // warp w owns 256 contiguous Morton-sorted points; lane handles 8 strided
    float xs[8], ys[8], zs[8], dist[8];
    int oidp[4];                                  // orig idx pairs (hi16|lo16)
    #pragma unroll
    for (int k = 0; k < 8; k++) {
        float4 f = S[w*256 + k*32 + lane];
        xs[k] = f.x; ys[k] = f.y; zs[k] = f.z;
        dist[k] = 1e10f;
        int oi = __float_as_int(f.w);
        if (k & 1) oidp[k>>1] |= oi << 16; else oidp[k>>1] = oi;
    }

    // warp AABB
    float lox = xs[0], hix = xs[0], loy = ys[0], hiy = ys[0], loz = zs[0], hiz = zs[0];
    #pragma unroll
    for (int k = 1; k < 8; k++) {
        lox = fminf(lox, xs[k]); hix = fmaxf(hix, xs[k]);
        loy = fminf(loy, ys[k]); hiy = fmaxf(hiy, ys[k]);
        loz = fminf(loz, zs[k]); hiz = fmaxf(hiz, zs[k]);
    }
    #pragma unroll
    for (int o = 16; o > 0; o >>= 1) {
        lox = fminf(lox, __shfl_xor_sync(0xffffffffu, lox, o));
        hix = fmaxf(hix, __shfl_xor_sync(0xffffffffu, hix, o));
        loy = fminf(loy, __shfl_xor_sync(0xffffffffu, loy, o));
        hiy = fmaxf(hiy, __shfl_xor_sync(0xffffffffu, hiy, o));
        loz = fminf(loz, __shfl_xor_sync(0xffffffffu, loz, o));
        hiz = fmaxf(hiz, __shfl_xor_sync(0xffffffffu, hiz, o));
    }

    __shared__ unsigned long long slot[3];
    if (tid < 3) slot[tid] = 0ull;

    float wbv = 1e30f;                            // warp's current max dist
    unsigned long long wkey = 0ull;

    float fx = P[0], fy = P[1], fz = P[2];        // far_0 = original index 0
    if (tid == 0) {
        g_newxyz[b*NPOINT*3 + 0] = fx;
        g_newxyz[b*NPOINT*3 + 1] = fy;
        g_newxyz[b*NPOINT*3 + 2] = fz;
    }
    __syncthreads();

    for (int s = 1; s < NPOINT; s++) {
        // lower bound dist(far, warp AABB)^2, deflated for fp safety
        float ax = fmaxf(fmaxf(lox - fx, fx - hix), 0.0f);
        float ay = fmaxf(fmaxf(loy - fy, fy - hiy), 0.0f);
        float az = fmaxf(fmaxf(loz - fz, fz - hiz), 0.0f);
        float lb = (ax*ax + ay*ay + az*az) * 0.999f;

        if (lb < wbv) {
            // exact update + lane argmax (tie -> smaller ORIGINAL index)
            float bv = -1.0f; int bi = 0x7fffffff;
            #pragma unroll
            for (int k = 0; k < 8; k++) {
                float d  = sqdist_rn(xs[k], ys[k], zs[k], fx, fy, fz);
                float nd = fminf(dist[k], d);
                dist[k]  = nd;
                int oi = (oidp[k>>1] >> ((k & 1) * 16)) & 0xFFFF;
                if (nd > bv || (nd == bv && oi < bi)) { bv = nd; bi = oi; }
            }
            // warp argmax: redux on dist bits, then redux on (8191-oi) among matches
            unsigned vb = __float_as_uint(bv);
            unsigned m  = __reduce_max_sync(0xffffffffu, vb);
            unsigned lo = (vb == m) ? (unsigned)(8191 - bi) : 0u;
            unsigned l  = __reduce_max_sync(0xffffffffu, lo);
            wkey = ((unsigned long long)m << 32) | l;
            wbv  = __uint_as_float(m);
        }
        // (pruned warps: dists unchanged -> cached wkey still valid)

        if (lane == 0) atomicMax(&slot[s % 3], wkey);
        __syncthreads();
        unsigned long long r = slot[s % 3];
        if (tid == 0) slot[(s + 2) % 3] = 0ull;   // reused at s+2; barrier s+1 orders
        int oi = 8191 - (int)(r & 0xFFFFFFFFull);
        fx = cx[oi]; fy = cy[oi]; fz = cz[oi];    // LDS, not LDG
        if (tid == 0) {
            g_newxyz[(b*NPOINT + s)*3 + 0] = fx;
            g_newxyz[(b*NPOINT + s)*3 + 1] = fy;
            g_newxyz[(b*NPOINT + s)*3 + 2] = fz;
        }
    }
}

// =====================  Repulsion: one thread per query point  =====================
#define RTILE 256

#define INSERT5(dv) do {                                   \
    float _d = (dv);                                       \
    if (_d < s4) { s4 = _d;                                \
        if (s4 < s3) { float _t = s3; s3 = s4; s4 = _t; }  \
        if (s3 < s2) { float _t = s2; s2 = s3; s3 = _t; }  \
        if (s2 < s1) { float _t = s1; s1 = s2; s2 = _t; }  \
        if (s1 < s0) { float _t = s0; s0 = s1; s1 = _t; }  \
    } } while (0)

__global__ void __launch_bounds__(RTILE)
repulsion_kernel(const float* __restrict__ pcd, float r2, float radius, float hh) {
    const int blocks_per_b = NPTS / RTILE;
    const int b  = blockIdx.x / blocks_per_b;
    const int qi = (blockIdx.x % blocks_per_b) * RTILE + threadIdx.x;
    const float* P = pcd + b * NPTS * 3;

    const float qx = P[3*qi], qy = P[3*qi+1], qz = P[3*qi+2];

    __shared__ float4 sp[RTILE];

    float s0 = 1e30f, s1 = 1e30f, s2 = 1e30f, s3 = 1e30f, s4 = 1e30f;
    int   c  = 0;
    float h0 = 0.0f;

    for (int t = 0; t < NPTS; t += RTILE) {
        int j = t + threadIdx.x;
        sp[threadIdx.x] = make_float4(P[3*j], P[3*j+1], P[3*j+2], 0.0f);
        __syncthreads();
        #pragma unroll 8
        for (int u = 0; u < RTILE; u++) {
            float4 p = sp[u];
            float d = sqdist_f(p.x, p.y, p.z, qx, qy, qz);
            if (d <= r2 && c < 20) {
                if (c == 0) h0 = d;
                c++;
                INSERT5(d);
            }
        }
        __syncthreads();
    }

    int pads = 20 - c;
    if (pads > 5) pads = 5;
    for (int k = 0; k < pads; k++) INSERT5(h0);

    float acc = 0.0f;
    acc += radius - sqrtf(s1) * expf(-(s1 / hh));
    acc += radius - sqrtf(s2) * expf(-(s2 / hh));
    acc += radius - sqrtf(s3) * expf(-(s3 / hh));
    acc += radius - sqrtf(s4) * expf(-(s4 / hh));

    float ws = warp_sum(acc);
    __shared__ float red[RTILE/32];
    if ((threadIdx.x & 31) == 0) red[threadIdx.x >> 5] = ws;
    __syncthreads();
    if (threadIdx.x == 0) {
        float tot = 0.0f;
        #pragma unroll
        for (int w = 0; w < RTILE/32; w++) tot += red[w];
        atomicAdd(&g_acc[1], (double)tot);
    }
}

// ==========  Uniform loss: one BLOCK per center, 4-warp split scan  ==========
struct ULevels {
    float  r2[5];
    float  el[5];
    float  den[5];
    double w[5];
    int    ns[5];
};

__device__ float eval_level(const float4* H, int n_stored, int true_cnt,
                            float r2, float el, float den, int ns, int lane)
{
    int u = true_cnt < ns ? true_cnt : ns;
    float lsum = 0.0f;
    int jstart = 0;
    if (u < ns) {
        if (lane == 0) {
            float ud = sqrtf(1e-8f);
            float t  = ud - el;
            lsum += (float)(ns - u + 1) * ((t * t) / den);
        }
        jstart = 1;
    }
    for (int j = jstart + lane; j < u; j += 32) {
        float xj = 0.f, yj = 0.f, zj = 0.f;
        int seen = 0;
        for (int i = 0; i < n_stored; i++) {
            float4 h = H[i];
            if (h.w <= r2) {
                if (seen == j) { xj = h.x; yj = h.y; zj = h.z; break; }
                seen++;
            }
        }
        float m1 = 1e30f;
        seen = 0;
        for (int i = 0; i < n_stored && seen < u; i++) {
            float4 h = H[i];
            if (h.w <= r2) {
                if (seen != j) {
                    float d = sqdist_f(h.x, h.y, h.z, xj, yj, zj);
                    m1 = fminf(m1, d);
                }
                seen++;
            }
        }
        float ud = sqrtf(fabsf(m1 + 1e-8f));
        float t  = ud - el;
        lsum += (t * t) / den;
    }
    return lsum;
}

__global__ void __launch_bounds__(128)
uniform_kernel(const float* __restrict__ pcd, ULevels L) {
    const int g    = blockIdx.x;
    const int b    = g / NPOINT;
    const int tid  = threadIdx.x;
    const int w    = tid >> 5;
    const int lane = tid & 31;
    const float* P = pcd + b * NPTS * 3;

    const float qx = g_newxyz[g*3], qy = g_newxyz[g*3+1], qz = g_newxyz[g*3+2];
    const float r2max = L.r2[4];

    __shared__ float4 Hseg[4*SEG];
    __shared__ float4 H[CAP];
    __shared__ int    s_cnt[4];

    int cnt = 0;
    const int start = w * (NPTS/4);
    for (int it = 0; it < (NPTS/4)/32; it++) {
        int j = start + it*32 + lane;
        float x = __ldg(&P[3*j]), y = __ldg(&P[3*j+1]), z = __ldg(&P[3*j+2]);
        float d = sqdist_f(x, y, z, qx, qy, qz);
        bool hit = (d <= r2max);
        unsigned m = __ballot_sync(0xffffffffu, hit);
        if (m) {
            if (hit) {
                int pos = cnt + __popc(m & ((1u << lane) - 1u));
                if (pos < SEG) Hseg[w*SEG + pos] = make_float4(x, y, z, d);
            }
            cnt += __popc(m);
        }
    }
    if (lane == 0) s_cnt[w] = cnt;
    __syncthreads();

    int c0 = s_cnt[0], c1 = s_cnt[1], c2 = s_cnt[2], c3 = s_cnt[3];
    bool ovf = (c0 > SEG) | (c1 > SEG) | (c2 > SEG) | (c3 > SEG);
    int tot = c0 + c1 + c2 + c3;

    if (!ovf) {
        int base = (w > 0 ? c0 : 0) + (w > 1 ? c1 : 0) + (w > 2 ? c2 : 0);
        int mycnt = s_cnt[w];
        for (int i = lane; i < mycnt; i += 32) H[base + i] = Hseg[w*SEG + i];
        __syncthreads();
        if (w == 0) {
            double acc = 0.0;
            #pragma unroll
            for (int k = 0; k < 5; k++) {
                float r2 = L.r2[k];
                int ck = 0;
                for (int i = lane; i < tot; i += 32) ck += (H[i].w <= r2) ? 1 : 0;
                #pragma unroll
                for (int o = 16; o > 0; o >>= 1)
                    ck += __shfl_down_sync(0xffffffffu, ck, o);
                ck = __shfl_sync(0xffffffffu, ck, 0);
                float lsum = eval_level(H, tot, ck, r2, L.el[k], L.den[k], L.ns[k], lane);
                acc += L.w[k] * (double)lsum;
            }
            #pragma unroll
            for (int o = 16; o > 0; o >>= 1)
                acc += __shfl_down_sync(0xffffffffu, acc, o);
            if (lane == 0) atomicAdd(&g_acc[0], acc);
        }
    } else {
        if (w == 0) {
            double acc = 0.0;
            for (int k = 0; k < 5; k++) {
                float r2 = L.r2[k];
                int ns = L.ns[k];
                int c = 0;
                for (int it = 0; it < NPTS/32; it++) {
                    int j = it*32 + lane;
                    float x = P[3*j], y = P[3*j+1], z = P[3*j+2];
                    float d = sqdist_f(x, y, z, qx, qy, qz);
                    bool hit = (d <= r2);
                    unsigned m = __ballot_sync(0xffffffffu, hit);
                    if (hit) {
                        int pos = c + __popc(m & ((1u << lane) - 1u));
                        if (pos < ns) H[pos] = make_float4(x, y, z, d);
                    }
                    c += __popc(m);
                }
                int stored = c < ns ? c : ns;
                float lsum = eval_level(H, stored, c, r2, L.el[k], L.den[k], ns, lane);
                acc += L.w[k] * (double)lsum;
            }
            #pragma unroll
            for (int o = 16; o > 0; o >>= 1)
                acc += __shfl_down_sync(0xffffffffu, acc, o);
            if (lane == 0) atomicAdd(&g_acc[0], acc);
        }
    }
}

__global__ void finalize_kernel(float* out) {
    out[0] = (float)g_acc[0];
    out[1] = (float)(g_acc[1] / (double)(NB * NPTS * 4));
}

// ============================  launch  ============================
#define FPS_SMEM (3 * NPTS * sizeof(float))   /* 96 KB */

static cudaStream_t g_s2;
static cudaEvent_t  g_ev0, g_ev1;
struct _StreamInit {
    _StreamInit() {
        cudaStreamCreateWithFlags(&g_s2, cudaStreamNonBlocking);
        cudaEventCreateWithFlags(&g_ev0, cudaEventDisableTiming);
        cudaEventCreateWithFlags(&g_ev1, cudaEventDisableTiming);
        cudaFuncSetAttribute(fps_kernel,
                             cudaFuncAttributeMaxDynamicSharedMemorySize,
                             (int)FPS_SMEM);
    }
};
static _StreamInit g_stream_init;

extern "C" void kernel_launch(void* const* d_in, const int* in_sizes, int n_in,
                              void* d_out, int out_size) {
    const float* pcd = (const float*)d_in[0];
    float* out = (float*)d_out;

    init_kernel<<<1, 1>>>();

    // fork: repulsion on side stream, concurrent with sort+FPS+uniform
    cudaEventRecord(g_ev0, 0);
    cudaStreamWaitEvent(g_s2, g_ev0, 0);
    {
        float r2     = (float)(0.07 * 0.07);
        float radius = (float)0.07;
        float hh     = (float)(0.03 * 0.03);
        repulsion_kernel<<<NB * (NPTS / RTILE), RTILE, 0, g_s2>>>(pcd, r2, radius, hh);
    }
    cudaEventRecord(g_ev1, g_s2);

    sort_kernel<<<NB, 1024>>>(pcd);
    fps_kernel<<<NB, 1024, FPS_SMEM>>>(pcd);

    {
        static const double PS[5] = {0.004, 0.008, 0.01, 0.012, 0.016};
        ULevels L;
        for (int k = 0; k < 5; k++) {
            double p  = PS[k];
            int    ns = (int)(8192.0 * p);
            double r  = sqrt(p * 1.0);
            double disk = M_PI * 1.0 * p / (double)ns;
            double el   = sqrt(2.0 * disk / 1.732);
            L.r2[k]  = (float)(r * r);
            L.el[k]  = (float)el;
            L.den[k] = (float)(el + 1e-8);
            L.w[k]   = (p * 100.0) * (p * 100.0) / ((double)NG * (double)ns) / 5.0;
            L.ns[k]  = ns;
        }
        uniform_kernel<<<NG, 128>>>(pcd, L);
    }

    cudaStreamWaitEvent(0, g_ev1, 0);
    finalize_kernel<<<1, 1>>>(out);
}

// round 8
// speedup vs baseline: 3.4054x; 1.1133x over previous
#include <cuda_runtime.h>
#include <math.h>

#define NB     4
#define NPTS   8192
#define NPOINT 409          /* int(8192*0.05) */
#define NG     (NB*NPOINT)  /* 1636 */
#define CAP    256
#define SEG    64

// ---------------- device scratch (no allocations allowed) ----------------
__device__ double g_acc[2];                   // [0]=uniform, [1]=repulsion sum
__device__ float  g_newxyz[NB*NPOINT*3];      // FPS centers
__device__ float4 g_sorted[NB*NPTS];          // Morton-sorted points (w = orig idx)

__global__ void init_kernel() { g_acc[0] = 0.0; g_acc[1] = 0.0; }

// exact-rounding distance (FPS argmax must match reference exactly)
__device__ __forceinline__ float sqdist_rn(float ax, float ay, float az,
                                           float bx, float by, float bz) {
    float dx = __fadd_rn(ax, -bx);
    float dy = __fadd_rn(ay, -by);
    float dz = __fadd_rn(az, -bz);
    return __fadd_rn(__fadd_rn(__fmul_rn(dx, dx), __fmul_rn(dy, dy)),
                     __fmul_rn(dz, dz));
}
// fast distance (FMA) — continuous-use sites only
__device__ __forceinline__ float sqdist_f(float ax, float ay, float az,
                                          float bx, float by, float bz) {
    float dx = ax - bx, dy = ay - by, dz = az - bz;
    return fmaf(dx, dx, fmaf(dy, dy, dz * dz));
}

__device__ __forceinline__ float warp_sum(float v) {
    #pragma unroll
    for (int o = 16; o > 0; o >>= 1) v += __shfl_down_sync(0xffffffffu, v, o);
    return v;
}

// =====================  Morton sort (u32 keys): one block per batch  =====================
__device__ __forceinline__ unsigned expandb(unsigned v) {
    v &= 1023u;
    v = (v | (v << 16)) & 0x030000FFu;
    v = (v | (v << 8))  & 0x0300F00Fu;
    v = (v | (v << 4))  & 0x030C30C3u;
    v = (v | (v << 2))  & 0x09249249u;
    return v;
}

__global__ void __launch_bounds__(1024, 1)
sort_kernel(const float* __restrict__ pcd) {
    __shared__ unsigned key[NPTS];                // 32 KB
    const int b   = blockIdx.x;
    const int tid = threadIdx.x;
    const float* P = pcd + b * NPTS * 3;

    for (int j = tid; j < NPTS; j += 1024) {
        float x = P[3*j], y = P[3*j+1], z = P[3*j+2];
        unsigned ux = (unsigned)fminf(fmaxf((x + 1.0f) * 32.0f, 0.0f), 63.0f);
        unsigned uy = (unsigned)fminf(fmaxf((y + 1.0f) * 32.0f, 0.0f), 63.0f);
        unsigned uz = (unsigned)fminf(fmaxf((z + 1.0f) * 32.0f, 0.0f), 63.0f);
        unsigned m = expandb(ux) | (expandb(uy) << 1) | (expandb(uz) << 2); // 18 bits
        key[j] = (m << 13) | (unsigned)j;
    }
    __syncthreads();

    for (int k = 2; k <= NPTS; k <<= 1) {
        for (int j = k >> 1; j > 0; j >>= 1) {
            for (int i = tid; i < NPTS; i += 1024) {
                int l = i ^ j;
                if (l > i) {
                    unsigned a = key[i], c = key[l];
                    bool up = ((i & k) == 0);
                    if ((a > c) == up) { key[i] = c; key[l] = a; }
                }
            }
            __syncthreads();
        }
    }

    for (int j = tid; j < NPTS; j += 1024) {
        int src = (int)(key[j] & 0x1FFFu);
        g_sorted[b*NPTS + j] =
            make_float4(P[3*src], P[3*src+1], P[3*src+2], __int_as_float(src));
    }
}

// ===========  FPS: warp AABB prune, float4 smem table, warp0 redux reduce  ===========
__global__ void __launch_bounds__(1024, 1)
fps_kernel(const float* __restrict__ pcd) {
    extern __shared__ float4 ctab[];              // [NPTS] orig-index coords, 128 KB

    const int b    = blockIdx.x;
    const int tid  = threadIdx.x;
    const int w    = tid >> 5;
    const int lane = tid & 31;
    const float4* S = g_sorted + b * NPTS;
    const float*  P = pcd + b * NPTS * 3;

    for (int j = tid; j < NPTS; j += 1024)
        ctab[j] = make_float4(P[3*j], P[3*j+1], P[3*j+2], 0.0f);

    // warp w owns 256 contiguous Morton-sorted points; lane handles 8 strided
    float xs[8], ys[8], zs[8], dist[8];
    unsigned loid[8];                             // 8191 - orig_idx (tie-break key)
    #pragma unroll
    for (int k = 0; k < 8; k++) {
        float4 f = S[w*256 + k*32 + lane];
        xs[k] = f.x; ys[k] = f.y; zs[k] = f.z;
        dist[k] = 1e10f;
        loid[k] = 8191u - (unsigned)__float_as_int(f.w);
    }

    // warp AABB
    float lox = xs[0], hix = xs[0], loy = ys[0], hiy = ys[0], loz = zs[0], hiz = zs[0];
    #pragma unroll
    for (int k = 1; k < 8; k++) {
        lox = fminf(lox, xs[k]); hix = fmaxf(hix, xs[k]);
        loy = fminf(loy, ys[k]); hiy = fmaxf(hiy, ys[k]);
        loz = fminf(loz, zs[k]); hiz = fmaxf(hiz, zs[k]);
    }
    #pragma unroll
    for (int o = 16; o > 0; o >>= 1) {
        lox = fminf(lox, __shfl_xor_sync(0xffffffffu, lox, o));
        hix = fmaxf(hix, __shfl_xor_sync(0xffffffffu, hix, o));
        loy = fminf(loy, __shfl_xor_sync(0xffffffffu, loy, o));
        hiy = fmaxf(hiy, __shfl_xor_sync(0xffffffffu, hiy, o));
        loz = fminf(loz, __shfl_xor_sync(0xffffffffu, loz, o));
        hiz = fmaxf(hiz, __shfl_xor_sync(0xffffffffu, hiz, o));
    }

    __shared__ unsigned long long skey[32];
    __shared__ float4 sF;

    float wbv = 1e30f;                            // warp's current max dist
    unsigned long long wkey = 0ull;

    float fx = P[0], fy = P[1], fz = P[2];        // far_0 = original index 0
    if (tid == 0) {
        g_newxyz[b*NPOINT*3 + 0] = fx;
        g_newxyz[b*NPOINT*3 + 1] = fy;
        g_newxyz[b*NPOINT*3 + 2] = fz;
    }
    __syncthreads();

    for (int s = 1; s < NPOINT; s++) {
        // lower bound dist(far, warp AABB)^2, deflated for fp safety
        float ax = fmaxf(fmaxf(lox - fx, fx - hix), 0.0f);
        float ay = fmaxf(fmaxf(loy - fy, fy - hiy), 0.0f);
        float az = fmaxf(fmaxf(loz - fz, fz - hiz), 0.0f);
        float lb = (ax*ax + ay*ay + az*az) * 0.999f;

        if (lb < wbv) {
            // exact update; lane max via u64 key (dist_bits << 32 | (8191-oi))
            unsigned long long kmax = 0ull;
            #pragma unroll
            for (int k = 0; k < 8; k++) {
                float d  = sqdist_rn(xs[k], ys[k], zs[k], fx, fy, fz);
                float nd = fminf(dist[k], d);
                dist[k]  = nd;
                unsigned long long kk =
                    ((unsigned long long)__float_as_uint(nd) << 32) | loid[k];
                kmax = kk > kmax ? kk : kmax;
            }
            // warp argmax: redux on dist bits, then redux on low among matches
            unsigned vb = (unsigned)(kmax >> 32);
            unsigned m  = __reduce_max_sync(0xffffffffu, vb);
            unsigned lo = (vb == m) ? (unsigned)kmax : 0u;
            unsigned l  = __reduce_max_sync(0xffffffffu, lo);
            wkey = ((unsigned long long)m << 32) | l;
            wbv  = __uint_as_float(m);
        }
        // (pruned warps: dists unchanged -> cached wkey still valid)

        if (lane == 0) skey[w] = wkey;
        __syncthreads();
        if (w == 0) {
            unsigned long long k = skey[lane];
            unsigned hi = (unsigned)(k >> 32);
            unsigned m  = __reduce_max_sync(0xffffffffu, hi);
            unsigned lo = (hi == m) ? (unsigned)k : 0u;
            unsigned l  = __reduce_max_sync(0xffffffffu, lo);
            if (lane == 0) {
                int oi = 8191 - (int)l;
                float4 c = ctab[oi];
                sF = c;
                g_newxyz[(b*NPOINT + s)*3 + 0] = c.x;
                g_newxyz[(b*NPOINT + s)*3 + 1] = c.y;
                g_newxyz[(b*NPOINT + s)*3 + 2] = c.z;
            }
        }
        __syncthreads();
        float4 c = sF;
        fx = c.x; fy = c.y; fz = c.z;
    }
}

// =====================  Repulsion: one thread per query point  =====================
#define RTILE 256

#define INSERT5(dv) do {                                   \
    float _d = (dv);                                       \
    if (_d < s4) { s4 = _d;                                \
        if (s4 < s3) { float _t = s3; s3 = s4; s4 = _t; }  \
        if (s3 < s2) { float _t = s2; s2 = s3; s3 = _t; }  \
        if (s2 < s1) { float _t = s1; s1 = s2; s2 = _t; }  \
        if (s1 < s0) { float _t = s0; s0 = s1; s1 = _t; }  \
    } } while (0)

__global__ void __launch_bounds__(RTILE)
repulsion_kernel(const float* __restrict__ pcd, float r2, float radius, float hh) {
    const int blocks_per_b = NPTS / RTILE;
    const int b  = blockIdx.x / blocks_per_b;
    const int qi = (blockIdx.x % blocks_per_b) * RTILE + threadIdx.x;
    const float* P = pcd + b * NPTS * 3;

    const float qx = P[3*qi], qy = P[3*qi+1], qz = P[3*qi+2];

    __shared__ float4 sp[RTILE];

    float s0 = 1e30f, s1 = 1e30f, s2 = 1e30f, s3 = 1e30f, s4 = 1e30f;
    int   c  = 0;
    float h0 = 0.0f;

    for (int t = 0; t < NPTS; t += RTILE) {
        int j = t + threadIdx.x;
        sp[threadIdx.x] = make_float4(P[3*j], P[3*j+1], P[3*j+2], 0.0f);
        __syncthreads();
        #pragma unroll 8
        for (int u = 0; u < RTILE; u++) {
            float4 p = sp[u];
            float d = sqdist_f(p.x, p.y, p.z, qx, qy, qz);
            if (d <= r2 && c < 20) {
                if (c == 0) h0 = d;
                c++;
                INSERT5(d);
            }
        }
        __syncthreads();
    }

    int pads = 20 - c;
    if (pads > 5) pads = 5;
    for (int k = 0; k < pads; k++) INSERT5(h0);

    float acc = 0.0f;
    acc += radius - sqrtf(s1) * expf(-(s1 / hh));
    acc += radius - sqrtf(s2) * expf(-(s2 / hh));
    acc += radius - sqrtf(s3) * expf(-(s3 / hh));
    acc += radius - sqrtf(s4) * expf(-(s4 / hh));

    float ws = warp_sum(acc);
    __shared__ float red[RTILE/32];
    if ((threadIdx.x & 31) == 0) red[threadIdx.x >> 5] = ws;
    __syncthreads();
    if (threadIdx.x == 0) {
        float tot = 0.0f;
        #pragma unroll
        for (int w = 0; w < RTILE/32; w++) tot += red[w];
        atomicAdd(&g_acc[1], (double)tot);
    }
}

// ==========  Uniform loss: one BLOCK per center, 4-warp split scan  ==========
struct ULevels {
    float  r2[5];
    float  el[5];
    float  den[5];
    double w[5];
    int    ns[5];
};

__device__ float eval_level(const float4* H, int n_stored, int true_cnt,
                            float r2, float el, float den, int ns, int lane)
{
    int u = true_cnt < ns ? true_cnt : ns;
    float lsum = 0.0f;
    int jstart = 0;
    if (u < ns) {
        if (lane == 0) {
            float ud = sqrtf(1e-8f);
            float t  = ud - el;
            lsum += (float)(ns - u + 1) * ((t * t) / den);
        }
        jstart = 1;
    }
    for (int j = jstart + lane; j < u; j += 32) {
        float xj = 0.f, yj = 0.f, zj = 0.f;
        int seen = 0;
        for (int i = 0; i < n_stored; i++) {
            float4 h = H[i];
            if (h.w <= r2) {
                if (seen == j) { xj = h.x; yj = h.y; zj = h.z; break; }
                seen++;
            }
        }
        float m1 = 1e30f;
        seen = 0;
        for (int i = 0; i < n_stored && seen < u; i++) {
            float4 h = H[i];
            if (h.w <= r2) {
                if (seen != j) {
                    float d = sqdist_f(h.x, h.y, h.z, xj, yj, zj);
                    m1 = fminf(m1, d);
                }
                seen++;
            }
        }
        float ud = sqrtf(fabsf(m1 + 1e-8f));
        float t  = ud - el;
        lsum += (t * t) / den;
    }
    return lsum;
}

__global__ void __launch_bounds__(128)
uniform_kernel(const float* __restrict__ pcd, ULevels L) {
    const int g    = blockIdx.x;
    const int b    = g / NPOINT;
    const int tid  = threadIdx.x;
    const int w    = tid >> 5;
    const int lane = tid & 31;
    const float* P = pcd + b * NPTS * 3;

    const float qx = g_newxyz[g*3], qy = g_newxyz[g*3+1], qz = g_newxyz[g*3+2];
    const float r2max = L.r2[4];

    __shared__ float4 Hseg[4*SEG];
    __shared__ float4 H[CAP];
    __shared__ int    s_cnt[4];

    int cnt = 0;
    const int start = w * (NPTS/4);
    for (int it = 0; it < (NPTS/4)/32; it++) {
        int j = start + it*32 + lane;
        float x = __ldg(&P[3*j]), y = __ldg(&P[3*j+1]), z = __ldg(&P[3*j+2]);
        float d = sqdist_f(x, y, z, qx, qy, qz);
        bool hit = (d <= r2max);
        unsigned m = __ballot_sync(0xffffffffu, hit);
        if (m) {
            if (hit) {
                int pos = cnt + __popc(m & ((1u << lane) - 1u));
                if (pos < SEG) Hseg[w*SEG + pos] = make_float4(x, y, z, d);
            }
            cnt += __popc(m);
        }
    }
    if (lane == 0) s_cnt[w] = cnt;
    __syncthreads();

    int c0 = s_cnt[0], c1 = s_cnt[1], c2 = s_cnt[2], c3 = s_cnt[3];
    bool ovf = (c0 > SEG) | (c1 > SEG) | (c2 > SEG) | (c3 > SEG);
    int tot = c0 + c1 + c2 + c3;

    if (!ovf) {
        int base = (w > 0 ? c0 : 0) + (w > 1 ? c1 : 0) + (w > 2 ? c2 : 0);
        int mycnt = s_cnt[w];
        for (int i = lane; i < mycnt; i += 32) H[base + i] = Hseg[w*SEG + i];
        __syncthreads();
        if (w == 0) {
            double acc = 0.0;
            #pragma unroll
            for (int k = 0; k < 5; k++) {
                float r2 = L.r2[k];
                int ck = 0;
                for (int i = lane; i < tot; i += 32) ck += (H[i].w <= r2) ? 1 : 0;
                #pragma unroll
                for (int o = 16; o > 0; o >>= 1)
                    ck += __shfl_down_sync(0xffffffffu, ck, o);
                ck = __shfl_sync(0xffffffffu, ck, 0);
                float lsum = eval_level(H, tot, ck, r2, L.el[k], L.den[k], L.ns[k], lane);
                acc += L.w[k] * (double)lsum;
            }
            #pragma unroll
            for (int o = 16; o > 0; o >>= 1)
                acc += __shfl_down_sync(0xffffffffu, acc, o);
            if (lane == 0) atomicAdd(&g_acc[0], acc);
        }
    } else {
        if (w == 0) {
            double acc = 0.0;
            for (int k = 0; k < 5; k++) {
                float r2 = L.r2[k];
                int ns = L.ns[k];
                int c = 0;
                for (int it = 0; it < NPTS/32; it++) {
                    int j = it*32 + lane;
                    float x = P[3*j], y = P[3*j+1], z = P[3*j+2];
                    float d = sqdist_f(x, y, z, qx, qy, qz);
                    bool hit = (d <= r2);
                    unsigned m = __ballot_sync(0xffffffffu, hit);
                    if (hit) {
                        int pos = c + __popc(m & ((1u << lane) - 1u));
                        if (pos < ns) H[pos] = make_float4(x, y, z, d);
                    }
                    c += __popc(m);
                }
                int stored = c < ns ? c : ns;
                float lsum = eval_level(H, stored, c, r2, L.el[k], L.den[k], ns, lane);
                acc += L.w[k] * (double)lsum;
            }
            #pragma unroll
            for (int o = 16; o > 0; o >>= 1)
                acc += __shfl_down_sync(0xffffffffu, acc, o);
            if (lane == 0) atomicAdd(&g_acc[0], acc);
        }
    }
}

__global__ void finalize_kernel(float* out) {
    out[0] = (float)g_acc[0];
    out[1] = (float)(g_acc[1] / (double)(NB * NPTS * 4));
}

// ============================  launch  ============================
#define FPS_SMEM (NPTS * sizeof(float4))   /* 128 KB */

static cudaStream_t g_s2;
static cudaEvent_t  g_ev0, g_ev1;
struct _StreamInit {
    _StreamInit() {
        cudaStreamCreateWithFlags(&g_s2, cudaStreamNonBlocking);
        cudaEventCreateWithFlags(&g_ev0, cudaEventDisableTiming);
        cudaEventCreateWithFlags(&g_ev1, cudaEventDisableTiming);
        cudaFuncSetAttribute(fps_kernel,
                             cudaFuncAttributeMaxDynamicSharedMemorySize,
                             (int)FPS_SMEM);
    }
};
static _StreamInit g_stream_init;

extern "C" void kernel_launch(void* const* d_in, const int* in_sizes, int n_in,
                              void* d_out, int out_size) {
    const float* pcd = (const float*)d_in[0];
    float* out = (float*)d_out;

    init_kernel<<<1, 1>>>();

    // fork: repulsion on side stream, concurrent with sort+FPS+uniform
    cudaEventRecord(g_ev0, 0);
    cudaStreamWaitEvent(g_s2, g_ev0, 0);
    {
        float r2     = (float)(0.07 * 0.07);
        float radius = (float)0.07;
        float hh     = (float)(0.03 * 0.03);
        repulsion_kernel<<<NB * (NPTS / RTILE), RTILE, 0, g_s2>>>(pcd, r2, radius, hh);
    }
    cudaEventRecord(g_ev1, g_s2);

    sort_kernel<<<NB, 1024>>>(pcd);
    fps_kernel<<<NB, 1024, FPS_SMEM>>>(pcd);

    {
        static const double PS[5] = {0.004, 0.008, 0.01, 0.012, 0.016};
        ULevels L;
        for (int k = 0; k < 5; k++) {
            double p  = PS[k];
            int    ns = (int)(8192.0 * p);
            double r  = sqrt(p * 1.0);
            double disk = M_PI * 1.0 * p / (double)ns;
            double el   = sqrt(2.0 * disk / 1.732);
            L.r2[k]  = (float)(r * r);
            L.el[k]  = (float)el;
            L.den[k] = (float)(el + 1e-8);
            L.w[k]   = (p * 100.0) * (p * 100.0) / ((double)NG * (double)ns) / 5.0;
            L.ns[k]  = ns;
        }
        uniform_kernel<<<NG, 128>>>(pcd, L);
    }

    cudaStreamWaitEvent(0, g_ev1, 0);
    finalize_kernel<<<1, 1>>>(out);
}

// round 9
// speedup vs baseline: 3.9269x; 1.1531x over previous
#include <cuda_runtime.h>
#include <math.h>

#define NB     4
#define NPTS   8192
#define NPOINT 409          /* int(8192*0.05) */
#define NG     (NB*NPOINT)  /* 1636 */
#define CAP    256
#define SEG    64

// ---------------- device scratch (no allocations allowed) ----------------
__device__ double g_acc[2];                   // [0]=uniform, [1]=repulsion sum
__device__ float  g_newxyz[NB*NPOINT*3];      // FPS centers
__device__ float4 g_sorted[NB*NPTS];          // Morton-sorted points (w = orig idx)

__global__ void init_kernel() { g_acc[0] = 0.0; g_acc[1] = 0.0; }

// exact-rounding distance (FPS argmax must match reference exactly)
__device__ __forceinline__ float sqdist_rn(float ax, float ay, float az,
                                           float bx, float by, float bz) {
    float dx = __fadd_rn(ax, -bx);
    float dy = __fadd_rn(ay, -by);
    float dz = __fadd_rn(az, -bz);
    return __fadd_rn(__fadd_rn(__fmul_rn(dx, dx), __fmul_rn(dy, dy)),
                     __fmul_rn(dz, dz));
}
// fast distance (FMA) — continuous-use sites only
__device__ __forceinline__ float sqdist_f(float ax, float ay, float az,
                                          float bx, float by, float bz) {
    float dx = ax - bx, dy = ay - by, dz = az - bz;
    return fmaf(dx, dx, fmaf(dy, dy, dz * dz));
}

__device__ __forceinline__ float warp_sum(float v) {
    #pragma unroll
    for (int o = 16; o > 0; o >>= 1) v += __shfl_down_sync(0xffffffffu, v, o);
    return v;
}

// =====================  Morton sort (u32 keys): one block per batch  =====================
__device__ __forceinline__ unsigned expandb(unsigned v) {
    v &= 1023u;
    v = (v | (v << 16)) & 0x030000FFu;
    v = (v | (v << 8))  & 0x0300F00Fu;
    v = (v | (v << 4))  & 0x030C30C3u;
    v = (v | (v << 2))  & 0x09249249u;
    return v;
}

__global__ void __launch_bounds__(1024, 1)
sort_kernel(const float* __restrict__ pcd) {
    __shared__ unsigned key[NPTS];                // 32 KB
    const int b   = blockIdx.x;
    const int tid = threadIdx.x;
    const float* P = pcd + b * NPTS * 3;

    for (int j = tid; j < NPTS; j += 1024) {
        float x = P[3*j], y = P[3*j+1], z = P[3*j+2];
        unsigned ux = (unsigned)fminf(fmaxf((x + 1.0f) * 32.0f, 0.0f), 63.0f);
        unsigned uy = (unsigned)fminf(fmaxf((y + 1.0f) * 32.0f, 0.0f), 63.0f);
        unsigned uz = (unsigned)fminf(fmaxf((z + 1.0f) * 32.0f, 0.0f), 63.0f);
        unsigned m = expandb(ux) | (expandb(uy) << 1) | (expandb(uz) << 2); // 18 bits
        key[j] = (m << 13) | (unsigned)j;
    }
    __syncthreads();

    for (int k = 2; k <= NPTS; k <<= 1) {
        for (int j = k >> 1; j > 0; j >>= 1) {
            for (int i = tid; i < NPTS; i += 1024) {
                int l = i ^ j;
                if (l > i) {
                    unsigned a = key[i], c = key[l];
                    bool up = ((i & k) == 0);
                    if ((a > c) == up) { key[i] = c; key[l] = a; }
                }
            }
            __syncthreads();
        }
    }

    for (int j = tid; j < NPTS; j += 1024) {
        int src = (int)(key[j] & 0x1FFFu);
        g_sorted[b*NPTS + j] =
            make_float4(P[3*src], P[3*src+1], P[3*src+2], __int_as_float(src));
    }
}

// ======  FPS: lane-granular AABB prune (contiguous pts), 1 barrier, redux  ======
__global__ void __launch_bounds__(1024, 1)
fps_kernel(const float* __restrict__ pcd) {
    extern __shared__ float4 ctab[];              // [NPTS] orig-index coords, 128 KB

    const int b    = blockIdx.x;
    const int tid  = threadIdx.x;
    const int w    = tid >> 5;
    const int lane = tid & 31;
    const float4* S = g_sorted + b * NPTS;
    const float*  P = pcd + b * NPTS * 3;

    for (int j = tid; j < NPTS; j += 1024)
        ctab[j] = make_float4(P[3*j], P[3*j+1], P[3*j+2], 0.0f);

    // lane owns 8 CONTIGUOUS Morton-sorted points [tid*8, tid*8+8)
    float xs[8], ys[8], zs[8], dist[8];
    unsigned loid[8];                             // 8191 - orig_idx (tie-break key)
    #pragma unroll
    for (int k = 0; k < 8; k++) {
        float4 f = S[tid*8 + k];
        xs[k] = f.x; ys[k] = f.y; zs[k] = f.z;
        dist[k] = 1e10f;
        loid[k] = 8191u - (unsigned)__float_as_int(f.w);
    }

    // lane AABB (tight: 8 contiguous Morton points)
    float lox = xs[0], hix = xs[0], loy = ys[0], hiy = ys[0], loz = zs[0], hiz = zs[0];
    #pragma unroll
    for (int k = 1; k < 8; k++) {
        lox = fminf(lox, xs[k]); hix = fmaxf(hix, xs[k]);
        loy = fminf(loy, ys[k]); hiy = fmaxf(hiy, ys[k]);
        loz = fminf(loz, zs[k]); hiz = fmaxf(hiz, zs[k]);
    }

    // lane cached state: max-dist over owned points + its best key
    float dmax = 1e10f;
    unsigned long long lkey;
    {
        unsigned best = 0;
        #pragma unroll
        for (int k = 0; k < 8; k++) best = loid[k] > best ? loid[k] : best;
        lkey = ((unsigned long long)__float_as_uint(1e10f) << 32) | best;
    }

    __shared__ unsigned long long skey[32];

    float fx = P[0], fy = P[1], fz = P[2];        // far_0 = original index 0
    if (tid == 0) {
        g_newxyz[b*NPOINT*3 + 0] = fx;
        g_newxyz[b*NPOINT*3 + 1] = fy;
        g_newxyz[b*NPOINT*3 + 2] = fz;
    }
    __syncthreads();

    for (int s = 1; s < NPOINT; s++) {
        // lane lower bound dist(far, lane AABB)^2, deflated for fp safety
        float ax = fmaxf(fmaxf(lox - fx, fx - hix), 0.0f);
        float ay = fmaxf(fmaxf(loy - fy, fy - hiy), 0.0f);
        float az = fmaxf(fmaxf(loz - fz, fz - hiz), 0.0f);
        float lb = (ax*ax + ay*ay + az*az) * 0.999f;
        bool active = lb < dmax;                  // else: no dist can change

        if (__ballot_sync(0xffffffffu, active)) {
            if (active) {
                unsigned long long kmax = 0ull;
                #pragma unroll
                for (int k = 0; k < 8; k++) {
                    float d  = sqdist_rn(xs[k], ys[k], zs[k], fx, fy, fz);
                    float nd = fminf(dist[k], d);
                    dist[k]  = nd;
                    unsigned long long kk =
                        ((unsigned long long)__float_as_uint(nd) << 32) | loid[k];
                    kmax = kk > kmax ? kk : kmax;
                }
                lkey = kmax;
                dmax = __uint_as_float((unsigned)(kmax >> 32));
            }
        }
        // warp argmax over (cached/updated) lane keys
        unsigned vb = (unsigned)(lkey >> 32);
        unsigned m  = __reduce_max_sync(0xffffffffu, vb);
        unsigned lo = (vb == m) ? (unsigned)lkey : 0u;
        unsigned l  = __reduce_max_sync(0xffffffffu, lo);

        if (lane == 0)
            skey[w] = ((unsigned long long)m << 32) | l;
        __syncthreads();
        // every warp redundantly reduces the 32 warp keys (no 2nd barrier)
        unsigned long long k = skey[lane];
        unsigned hi2 = (unsigned)(k >> 32);
        unsigned m2  = __reduce_max_sync(0xffffffffu, hi2);
        unsigned lo2 = (hi2 == m2) ? (unsigned)k : 0u;
        unsigned l2  = __reduce_max_sync(0xffffffffu, lo2);
        int oi = 8191 - (int)l2;
        float4 c = ctab[oi];                      // same addr warp-wide: broadcast
        fx = c.x; fy = c.y; fz = c.z;
        if (tid == 0) {
            g_newxyz[(b*NPOINT + s)*3 + 0] = fx;
            g_newxyz[(b*NPOINT + s)*3 + 1] = fy;
            g_newxyz[(b*NPOINT + s)*3 + 2] = fz;
        }
    }
}

// =====================  Repulsion: one thread per query point  =====================
#define RTILE 256

#define INSERT5(dv) do {                                   \
    float _d = (dv);                                       \
    if (_d < s4) { s4 = _d;                                \
        if (s4 < s3) { float _t = s3; s3 = s4; s4 = _t; }  \
        if (s3 < s2) { float _t = s2; s2 = s3; s3 = _t; }  \
        if (s2 < s1) { float _t = s1; s1 = s2; s2 = _t; }  \
        if (s1 < s0) { float _t = s0; s0 = s1; s1 = _t; }  \
    } } while (0)

__global__ void __launch_bounds__(RTILE)
repulsion_kernel(const float* __restrict__ pcd, float r2, float radius, float hh) {
    const int blocks_per_b = NPTS / RTILE;
    const int b  = blockIdx.x / blocks_per_b;
    const int qi = (blockIdx.x % blocks_per_b) * RTILE + threadIdx.x;
    const float* P = pcd + b * NPTS * 3;

    const float qx = P[3*qi], qy = P[3*qi+1], qz = P[3*qi+2];

    __shared__ float4 sp[RTILE];

    float s0 = 1e30f, s1 = 1e30f, s2 = 1e30f, s3 = 1e30f, s4 = 1e30f;
    int   c  = 0;
    float h0 = 0.0f;

    for (int t = 0; t < NPTS; t += RTILE) {
        int j = t + threadIdx.x;
        sp[threadIdx.x] = make_float4(P[3*j], P[3*j+1], P[3*j+2], 0.0f);
        __syncthreads();
        #pragma unroll 8
        for (int u = 0; u < RTILE; u++) {
            float4 p = sp[u];
            float d = sqdist_f(p.x, p.y, p.z, qx, qy, qz);
            if (d <= r2 && c < 20) {
                if (c == 0) h0 = d;
                c++;
                INSERT5(d);
            }
        }
        __syncthreads();
    }

    int pads = 20 - c;
    if (pads > 5) pads = 5;
    for (int k = 0; k < pads; k++) INSERT5(h0);

    float acc = 0.0f;
    acc += radius - sqrtf(s1) * expf(-(s1 / hh));
    acc += radius - sqrtf(s2) * expf(-(s2 / hh));
    acc += radius - sqrtf(s3) * expf(-(s3 / hh));
    acc += radius - sqrtf(s4) * expf(-(s4 / hh));

    float ws = warp_sum(acc);
    __shared__ float red[RTILE/32];
    if ((threadIdx.x & 31) == 0) red[threadIdx.x >> 5] = ws;
    __syncthreads();
    if (threadIdx.x == 0) {
        float tot = 0.0f;
        #pragma unroll
        for (int w = 0; w < RTILE/32; w++) tot += red[w];
        atomicAdd(&g_acc[1], (double)tot);
    }
}

// ==========  Uniform loss: one BLOCK per center, 4-warp split scan  ==========
struct ULevels {
    float  r2[5];
    float  el[5];
    float  den[5];
    double w[5];
    int    ns[5];
};

__device__ float eval_level(const float4* H, int n_stored, int true_cnt,
                            float r2, float el, float den, int ns, int lane)
{
    int u = true_cnt < ns ? true_cnt : ns;
    float lsum = 0.0f;
    int jstart = 0;
    if (u < ns) {
        if (lane == 0) {
            float ud = sqrtf(1e-8f);
            float t  = ud - el;
            lsum += (float)(ns - u + 1) * ((t * t) / den);
        }
        jstart = 1;
    }
    for (int j = jstart + lane; j < u; j += 32) {
        float xj = 0.f, yj = 0.f, zj = 0.f;
        int seen = 0;
        for (int i = 0; i < n_stored; i++) {
            float4 h = H[i];
            if (h.w <= r2) {
                if (seen == j) { xj = h.x; yj = h.y; zj = h.z; break; }
                seen++;
            }
        }
        float m1 = 1e30f;
        seen = 0;
        for (int i = 0; i < n_stored && seen < u; i++) {
            float4 h = H[i];
            if (h.w <= r2) {
                if (seen != j) {
                    float d = sqdist_f(h.x, h.y, h.z, xj, yj, zj);
                    m1 = fminf(m1, d);
                }
                seen++;
            }
        }
        float ud = sqrtf(fabsf(m1 + 1e-8f));
        float t  = ud - el;
        lsum += (t * t) / den;
    }
    return lsum;
}

__global__ void __launch_bounds__(128)
uniform_kernel(const float* __restrict__ pcd, ULevels L) {
    const int g    = blockIdx.x;
    const int b    = g / NPOINT;
    const int tid  = threadIdx.x;
    const int w    = tid >> 5;
    const int lane = tid & 31;
    const float* P = pcd + b * NPTS * 3;

    const float qx = g_newxyz[g*3], qy = g_newxyz[g*3+1], qz = g_newxyz[g*3+2];
    const float r2max = L.r2[4];

    __shared__ float4 Hseg[4*SEG];
    __shared__ float4 H[CAP];
    __shared__ int    s_cnt[4];

    int cnt = 0;
    const int start = w * (NPTS/4);
    for (int it = 0; it < (NPTS/4)/32; it++) {
        int j = start + it*32 + lane;
        float x = __ldg(&P[3*j]), y = __ldg(&P[3*j+1]), z = __ldg(&P[3*j+2]);
        float d = sqdist_f(x, y, z, qx, qy, qz);
        bool hit = (d <= r2max);
        unsigned m = __ballot_sync(0xffffffffu, hit);
        if (m) {
            if (hit) {
                int pos = cnt + __popc(m & ((1u << lane) - 1u));
                if (pos < SEG) Hseg[w*SEG + pos] = make_float4(x, y, z, d);
            }
            cnt += __popc(m);
        }
    }
    if (lane == 0) s_cnt[w] = cnt;
    __syncthreads();

    int c0 = s_cnt[0], c1 = s_cnt[1], c2 = s_cnt[2], c3 = s_cnt[3];
    bool ovf = (c0 > SEG) | (c1 > SEG) | (c2 > SEG) | (c3 > SEG);
    int tot = c0 + c1 + c2 + c3;

    if (!ovf) {
        int base = (w > 0 ? c0 : 0) + (w > 1 ? c1 : 0) + (w > 2 ? c2 : 0);
        int mycnt = s_cnt[w];
        for (int i = lane; i < mycnt; i += 32) H[base + i] = Hseg[w*SEG + i];
        __syncthreads();
        if (w == 0) {
            double acc = 0.0;
            #pragma unroll
            for (int k = 0; k < 5; k++) {
                float r2 = L.r2[k];
                int ck = 0;
                for (int i = lane; i < tot; i += 32) ck += (H[i].w <= r2) ? 1 : 0;
                #pragma unroll
                for (int o = 16; o > 0; o >>= 1)
                    ck += __shfl_down_sync(0xffffffffu, ck, o);
                ck = __shfl_sync(0xffffffffu, ck, 0);
                float lsum = eval_level(H, tot, ck, r2, L.el[k], L.den[k], L.ns[k], lane);
                acc += L.w[k] * (double)lsum;
            }
            #pragma unroll
            for (int o = 16; o > 0; o >>= 1)
                acc += __shfl_down_sync(0xffffffffu, acc, o);
            if (lane == 0) atomicAdd(&g_acc[0], acc);
        }
    } else {
        if (w == 0) {
            double acc = 0.0;
            for (int k = 0; k < 5; k++) {
                float r2 = L.r2[k];
                int ns = L.ns[k];
                int c = 0;
                for (int it = 0; it < NPTS/32; it++) {
                    int j = it*32 + lane;
                    float x = P[3*j], y = P[3*j+1], z = P[3*j+2];
                    float d = sqdist_f(x, y, z, qx, qy, qz);
                    bool hit = (d <= r2);
                    unsigned m = __ballot_sync(0xffffffffu, hit);
                    if (hit) {
                        int pos = c + __popc(m & ((1u << lane) - 1u));
                        if (pos < ns) H[pos] = make_float4(x, y, z, d);
                    }
                    c += __popc(m);
                }
                int stored = c < ns ? c : ns;
                float lsum = eval_level(H, stored, c, r2, L.el[k], L.den[k], ns, lane);
                acc += L.w[k] * (double)lsum;
            }
            #pragma unroll
            for (int o = 16; o > 0; o >>= 1)
                acc += __shfl_down_sync(0xffffffffu, acc, o);
            if (lane == 0) atomicAdd(&g_acc[0], acc);
        }
    }
}

__global__ void finalize_kernel(float* out) {
    out[0] = (float)g_acc[0];
    out[1] = (float)(g_acc[1] / (double)(NB * NPTS * 4));
}

// ============================  launch  ============================
#define FPS_SMEM (NPTS * sizeof(float4))   /* 128 KB */

static cudaStream_t g_s2;
static cudaEvent_t  g_ev0, g_ev1;
struct _StreamInit {
    _StreamInit() {
        cudaStreamCreateWithFlags(&g_s2, cudaStreamNonBlocking);
        cudaEventCreateWithFlags(&g_ev0, cudaEventDisableTiming);
        cudaEventCreateWithFlags(&g_ev1, cudaEventDisableTiming);
        cudaFuncSetAttribute(fps_kernel,
                             cudaFuncAttributeMaxDynamicSharedMemorySize,
                             (int)FPS_SMEM);
    }
};
static _StreamInit g_stream_init;

extern "C" void kernel_launch(void* const* d_in, const int* in_sizes, int n_in,
                              void* d_out, int out_size) {
    const float* pcd = (const float*)d_in[0];
    float* out = (float*)d_out;

    init_kernel<<<1, 1>>>();

    // fork: repulsion on side stream, concurrent with sort+FPS+uniform
    cudaEventRecord(g_ev0, 0);
    cudaStreamWaitEvent(g_s2, g_ev0, 0);
    {
        float r2     = (float)(0.07 * 0.07);
        float radius = (float)0.07;
        float hh     = (float)(0.03 * 0.03);
        repulsion_kernel<<<NB * (NPTS / RTILE), RTILE, 0, g_s2>>>(pcd, r2, radius, hh);
    }
    cudaEventRecord(g_ev1, g_s2);

    sort_kernel<<<NB, 1024>>>(pcd);
    fps_kernel<<<NB, 1024, FPS_SMEM>>>(pcd);

    {
        static const double PS[5] = {0.004, 0.008, 0.01, 0.012, 0.016};
        ULevels L;
        for (int k = 0; k < 5; k++) {
            double p  = PS[k];
            int    ns = (int)(8192.0 * p);
            double r  = sqrt(p * 1.0);
            double disk = M_PI * 1.0 * p / (double)ns;
            double el   = sqrt(2.0 * disk / 1.732);
            L.r2[k]  = (float)(r * r);
            L.el[k]  = (float)el;
            L.den[k] = (float)(el + 1e-8);
            L.w[k]   = (p * 100.0) * (p * 100.0) / ((double)NG * (double)ns) / 5.0;
            L.ns[k]  = ns;
        }
        uniform_kernel<<<NG, 128>>>(pcd, L);
    }

    cudaStreamWaitEvent(0, g_ev1, 0);
    finalize_kernel<<<1, 1>>>(out);
}

// round 10
// speedup vs baseline: 4.0090x; 1.0209x over previous
#include <cuda_runtime.h>
#include <math.h>

#define NB     4
#define NPTS   8192
#define NPOINT 409          /* int(8192*0.05) */
#define NG     (NB*NPOINT)  /* 1636 */
#define CAP    256
#define SEG    64

// ---------------- device scratch (no allocations allowed) ----------------
__device__ double g_acc[2];                   // [0]=uniform, [1]=repulsion sum
__device__ float  g_newxyz[NB*NPOINT*3];      // FPS centers
__device__ float4 g_sorted[NB*NPTS];          // Morton-sorted points (w = orig idx)
__device__ float4 g_pcd4[NB*NPTS];            // original-order points, float4

__global__ void init_kernel() { g_acc[0] = 0.0; g_acc[1] = 0.0; }

// exact-rounding distance (FPS argmax must match reference exactly)
__device__ __forceinline__ float sqdist_rn(float ax, float ay, float az,
                                           float bx, float by, float bz) {
    float dx = __fadd_rn(ax, -bx);
    float dy = __fadd_rn(ay, -by);
    float dz = __fadd_rn(az, -bz);
    return __fadd_rn(__fadd_rn(__fmul_rn(dx, dx), __fmul_rn(dy, dy)),
                     __fmul_rn(dz, dz));
}
// fast distance (FMA) — continuous-use sites only
__device__ __forceinline__ float sqdist_f(float ax, float ay, float az,
                                          float bx, float by, float bz) {
    float dx = ax - bx, dy = ay - by, dz = az - bz;
    return fmaf(dx, dx, fmaf(dy, dy, dz * dz));
}

__device__ __forceinline__ float warp_sum(float v) {
    #pragma unroll
    for (int o = 16; o > 0; o >>= 1) v += __shfl_down_sync(0xffffffffu, v, o);
    return v;
}

// =====================  Morton sort (u32 keys): one block per batch  =====================
__device__ __forceinline__ unsigned expandb(unsigned v) {
    v &= 1023u;
    v = (v | (v << 16)) & 0x030000FFu;
    v = (v | (v << 8))  & 0x0300F00Fu;
    v = (v | (v << 4))  & 0x030C30C3u;
    v = (v | (v << 2))  & 0x09249249u;
    return v;
}

__global__ void __launch_bounds__(1024, 1)
sort_kernel(const float* __restrict__ pcd) {
    __shared__ unsigned key[NPTS];                // 32 KB
    const int b   = blockIdx.x;
    const int tid = threadIdx.x;
    const float* P = pcd + b * NPTS * 3;

    for (int j = tid; j < NPTS; j += 1024) {
        float x = P[3*j], y = P[3*j+1], z = P[3*j+2];
        g_pcd4[b*NPTS + j] = make_float4(x, y, z, 0.0f);
        unsigned ux = (unsigned)fminf(fmaxf((x + 1.0f) * 32.0f, 0.0f), 63.0f);
        unsigned uy = (unsigned)fminf(fmaxf((y + 1.0f) * 32.0f, 0.0f), 63.0f);
        unsigned uz = (unsigned)fminf(fmaxf((z + 1.0f) * 32.0f, 0.0f), 63.0f);
        unsigned m = expandb(ux) | (expandb(uy) << 1) | (expandb(uz) << 2); // 18 bits
        key[j] = (m << 13) | (unsigned)j;
    }
    __syncthreads();

    for (int k = 2; k <= NPTS; k <<= 1) {
        for (int j = k >> 1; j > 0; j >>= 1) {
            for (int i = tid; i < NPTS; i += 1024) {
                int l = i ^ j;
                if (l > i) {
                    unsigned a = key[i], c = key[l];
                    bool up = ((i & k) == 0);
                    if ((a > c) == up) { key[i] = c; key[l] = a; }
                }
            }
            __syncthreads();
        }
    }

    for (int j = tid; j < NPTS; j += 1024) {
        int src = (int)(key[j] & 0x1FFFu);
        g_sorted[b*NPTS + j] =
            make_float4(P[3*src], P[3*src+1], P[3*src+2], __int_as_float(src));
    }
}

// ======  FPS: 512 thr, 2×8-pt AABB groups/lane, cached warp keys, redux  ======
__global__ void __launch_bounds__(512, 1)
fps_kernel(const float* __restrict__ pcd) {
    extern __shared__ float4 ctab[];              // [NPTS] orig-index coords, 128 KB

    const int b    = blockIdx.x;
    const int tid  = threadIdx.x;
    const int w    = tid >> 5;                    // 0..15
    const int lane = tid & 31;
    const float4* S  = g_sorted + b * NPTS;
    const float4* P4 = g_pcd4  + b * NPTS;
    const float*  P  = pcd + b * NPTS * 3;

    for (int j = tid; j < NPTS; j += 512)
        ctab[j] = P4[j];

    // lane owns 16 CONTIGUOUS Morton points [tid*16, tid*16+16) as 2 groups of 8
    float xs[16], ys[16], zs[16], dist[16];
    unsigned loid[16];                            // 8191 - orig_idx
    #pragma unroll
    for (int k = 0; k < 16; k++) {
        float4 f = S[tid*16 + k];
        xs[k] = f.x; ys[k] = f.y; zs[k] = f.z;
        dist[k] = 1e10f;
        loid[k] = 8191u - (unsigned)__float_as_int(f.w);
    }

    // per-group AABBs
    float lox0=xs[0],hix0=xs[0],loy0=ys[0],hiy0=ys[0],loz0=zs[0],hiz0=zs[0];
    float lox1=xs[8],hix1=xs[8],loy1=ys[8],hiy1=ys[8],loz1=zs[8],hiz1=zs[8];
    #pragma unroll
    for (int k = 1; k < 8; k++) {
        lox0=fminf(lox0,xs[k]);   hix0=fmaxf(hix0,xs[k]);
        loy0=fminf(loy0,ys[k]);   hiy0=fmaxf(hiy0,ys[k]);
        loz0=fminf(loz0,zs[k]);   hiz0=fmaxf(hiz0,zs[k]);
        lox1=fminf(lox1,xs[8+k]); hix1=fmaxf(hix1,xs[8+k]);
        loy1=fminf(loy1,ys[8+k]); hiy1=fmaxf(hiy1,ys[8+k]);
        loz1=fminf(loz1,zs[8+k]); hiz1=fmaxf(hiz1,zs[8+k]);
    }

    // per-group cached keys (max dist | tie-break) and lane key
    unsigned long long gkey0, gkey1, lkey;
    {
        unsigned b0 = 0, b1 = 0;
        #pragma unroll
        for (int k = 0; k < 8; k++) {
            b0 = loid[k]   > b0 ? loid[k]   : b0;
            b1 = loid[8+k] > b1 ? loid[8+k] : b1;
        }
        unsigned long long hi = (unsigned long long)__float_as_uint(1e10f) << 32;
        gkey0 = hi | b0; gkey1 = hi | b1;
        lkey  = gkey0 > gkey1 ? gkey0 : gkey1;
    }
    float dmax0 = 1e10f, dmax1 = 1e10f;

    __shared__ unsigned long long skey[32];
    if (tid < 32) skey[tid] = 0ull;               // lanes 16..31 stay 0 (never win)

    float fx = P[0], fy = P[1], fz = P[2];        // far_0 = original index 0
    if (tid == 0) {
        g_newxyz[b*NPOINT*3 + 0] = fx;
        g_newxyz[b*NPOINT*3 + 1] = fy;
        g_newxyz[b*NPOINT*3 + 2] = fz;
    }
    __syncthreads();

    for (int s = 1; s < NPOINT; s++) {
        // per-group lower bounds (deflated for fp safety)
        float ax0 = fmaxf(fmaxf(lox0 - fx, fx - hix0), 0.0f);
        float ay0 = fmaxf(fmaxf(loy0 - fy, fy - hiy0), 0.0f);
        float az0 = fmaxf(fmaxf(loz0 - fz, fz - hiz0), 0.0f);
        bool a0 = (ax0*ax0 + ay0*ay0 + az0*az0) * 0.999f < dmax0;
        float ax1 = fmaxf(fmaxf(lox1 - fx, fx - hix1), 0.0f);
        float ay1 = fmaxf(fmaxf(loy1 - fy, fy - hiy1), 0.0f);
        float az1 = fmaxf(fmaxf(loz1 - fz, fz - hiz1), 0.0f);
        bool a1 = (ax1*ax1 + ay1*ay1 + az1*az1) * 0.999f < dmax1;

        if (__ballot_sync(0xffffffffu, a0 | a1)) {
            if (a0) {
                unsigned long long kmax = 0ull;
                #pragma unroll
                for (int k = 0; k < 8; k++) {
                    float d  = sqdist_rn(xs[k], ys[k], zs[k], fx, fy, fz);
                    float nd = fminf(dist[k], d);
                    dist[k]  = nd;
                    unsigned long long kk =
                        ((unsigned long long)__float_as_uint(nd) << 32) | loid[k];
                    kmax = kk > kmax ? kk : kmax;
                }
                gkey0 = kmax;
                dmax0 = __uint_as_float((unsigned)(kmax >> 32));
            }
            if (a1) {
                unsigned long long kmax = 0ull;
                #pragma unroll
                for (int k = 0; k < 8; k++) {
                    float d  = sqdist_rn(xs[8+k], ys[8+k], zs[8+k], fx, fy, fz);
                    float nd = fminf(dist[8+k], d);
                    dist[8+k] = nd;
                    unsigned long long kk =
                        ((unsigned long long)__float_as_uint(nd) << 32) | loid[8+k];
                    kmax = kk > kmax ? kk : kmax;
                }
                gkey1 = kmax;
                dmax1 = __uint_as_float((unsigned)(kmax >> 32));
            }
            if (a0 | a1) lkey = gkey0 > gkey1 ? gkey0 : gkey1;
            // warp argmax (only when warp has an active lane; else skey stale-valid)
            unsigned vb = (unsigned)(lkey >> 32);
            unsigned m  = __reduce_max_sync(0xffffffffu, vb);
            unsigned lo = (vb == m) ? (unsigned)lkey : 0u;
            unsigned l  = __reduce_max_sync(0xffffffffu, lo);
            if (lane == 0)
                skey[w] = ((unsigned long long)m << 32) | l;
        }
        __syncthreads();
        // every warp redundantly reduces the 16 warp keys (no 2nd barrier)
        unsigned long long k = skey[lane];
        unsigned hi2 = (unsigned)(k >> 32);
        unsigned m2  = __reduce_max_sync(0xffffffffu, hi2);
        unsigned lo2 = (hi2 == m2) ? (unsigned)k : 0u;
        unsigned l2  = __reduce_max_sync(0xffffffffu, lo2);
        int oi = 8191 - (int)l2;
        float4 c = ctab[oi];                      // same addr warp-wide: broadcast
        fx = c.x; fy = c.y; fz = c.z;
        if (tid == 0) {
            g_newxyz[(b*NPOINT + s)*3 + 0] = fx;
            g_newxyz[(b*NPOINT + s)*3 + 1] = fy;
            g_newxyz[(b*NPOINT + s)*3 + 2] = fz;
        }
    }
}

// =====================  Repulsion: one thread per query point  =====================
#define RTILE 256

#define INSERT5(dv) do {                                   \
    float _d = (dv);                                       \
    if (_d < s4) { s4 = _d;                                \
        if (s4 < s3) { float _t = s3; s3 = s4; s4 = _t; }  \
        if (s3 < s2) { float _t = s2; s2 = s3; s3 = _t; }  \
        if (s2 < s1) { float _t = s1; s1 = s2; s2 = _t; }  \
        if (s1 < s0) { float _t = s0; s0 = s1; s1 = _t; }  \
    } } while (0)

__global__ void __launch_bounds__(RTILE)
repulsion_kernel(const float* __restrict__ pcd, float r2, float radius, float hh) {
    const int blocks_per_b = NPTS / RTILE;
    const int b  = blockIdx.x / blocks_per_b;
    const int qi = (blockIdx.x % blocks_per_b) * RTILE + threadIdx.x;
    const float* P = pcd + b * NPTS * 3;

    const float qx = P[3*qi], qy = P[3*qi+1], qz = P[3*qi+2];

    __shared__ float4 sp[RTILE];

    float s0 = 1e30f, s1 = 1e30f, s2 = 1e30f, s3 = 1e30f, s4 = 1e30f;
    int   c  = 0;
    float h0 = 0.0f;

    for (int t = 0; t < NPTS; t += RTILE) {
        int j = t + threadIdx.x;
        sp[threadIdx.x] = make_float4(P[3*j], P[3*j+1], P[3*j+2], 0.0f);
        __syncthreads();
        #pragma unroll 8
        for (int u = 0; u < RTILE; u++) {
            float4 p = sp[u];
            float d = sqdist_f(p.x, p.y, p.z, qx, qy, qz);
            if (d <= r2 && c < 20) {
                if (c == 0) h0 = d;
                c++;
                INSERT5(d);
            }
        }
        __syncthreads();
    }

    int pads = 20 - c;
    if (pads > 5) pads = 5;
    for (int k = 0; k < pads; k++) INSERT5(h0);

    float acc = 0.0f;
    acc += radius - sqrtf(s1) * expf(-(s1 / hh));
    acc += radius - sqrtf(s2) * expf(-(s2 / hh));
    acc += radius - sqrtf(s3) * expf(-(s3 / hh));
    acc += radius - sqrtf(s4) * expf(-(s4 / hh));

    float ws = warp_sum(acc);
    __shared__ float red[RTILE/32];
    if ((threadIdx.x & 31) == 0) red[threadIdx.x >> 5] = ws;
    __syncthreads();
    if (threadIdx.x == 0) {
        float tot = 0.0f;
        #pragma unroll
        for (int w = 0; w < RTILE/32; w++) tot += red[w];
        atomicAdd(&g_acc[1], (double)tot);
    }
}

// ==========  Uniform loss: one BLOCK per center, 4-warp split scan  ==========
struct ULevels {
    float  r2[5];
    float  el[5];
    float  den[5];
    double w[5];
    int    ns[5];
};

__device__ float eval_level(const float4* H, int n_stored, int true_cnt,
                            float r2, float el, float den, int ns, int lane)
{
    int u = true_cnt < ns ? true_cnt : ns;
    float lsum = 0.0f;
    int jstart = 0;
    if (u < ns) {
        if (lane == 0) {
            float ud = sqrtf(1e-8f);
            float t  = ud - el;
            lsum += (float)(ns - u + 1) * ((t * t) / den);
        }
        jstart = 1;
    }
    for (int j = jstart + lane; j < u; j += 32) {
        float xj = 0.f, yj = 0.f, zj = 0.f;
        int seen = 0;
        for (int i = 0; i < n_stored; i++) {
            float4 h = H[i];
            if (h.w <= r2) {
                if (seen == j) { xj = h.x; yj = h.y; zj = h.z; break; }
                seen++;
            }
        }
        float m1 = 1e30f;
        seen = 0;
        for (int i = 0; i < n_stored && seen < u; i++) {
            float4 h = H[i];
            if (h.w <= r2) {
                if (seen != j) {
                    float d = sqdist_f(h.x, h.y, h.z, xj, yj, zj);
                    m1 = fminf(m1, d);
                }
                seen++;
            }
        }
        float ud = sqrtf(fabsf(m1 + 1e-8f));
        float t  = ud - el;
        lsum += (t * t) / den;
    }
    return lsum;
}

__global__ void __launch_bounds__(128)
uniform_kernel(ULevels L) {
    const int g    = blockIdx.x;
    const int b    = g / NPOINT;
    const int tid  = threadIdx.x;
    const int w    = tid >> 5;
    const int lane = tid & 31;
    const float4* P4 = g_pcd4 + b * NPTS;

    const float qx = g_newxyz[g*3], qy = g_newxyz[g*3+1], qz = g_newxyz[g*3+2];
    const float r2max = L.r2[4];

    __shared__ float4 Hseg[4*SEG];
    __shared__ float4 H[CAP];
    __shared__ int    s_cnt[4];

    int cnt = 0;
    const int start = w * (NPTS/4);
    for (int it = 0; it < (NPTS/4)/64; it++) {      // unroll x2: 2 pts in flight
        int j0 = start + it*64 + lane;
        int j1 = j0 + 32;
        float4 f0 = P4[j0];
        float4 f1 = P4[j1];
        float d0 = sqdist_f(f0.x, f0.y, f0.z, qx, qy, qz);
        float d1 = sqdist_f(f1.x, f1.y, f1.z, qx, qy, qz);
        bool h0 = (d0 <= r2max);
        unsigned m0 = __ballot_sync(0xffffffffu, h0);
        if (m0) {
            if (h0) {
                int pos = cnt + __popc(m0 & ((1u << lane) - 1u));
                if (pos < SEG) Hseg[w*SEG + pos] = make_float4(f0.x, f0.y, f0.z, d0);
            }
            cnt += __popc(m0);
        }
        bool h1 = (d1 <= r2max);
        unsigned m1 = __ballot_sync(0xffffffffu, h1);
        if (m1) {
            if (h1) {
                int pos = cnt + __popc(m1 & ((1u << lane) - 1u));
                if (pos < SEG) Hseg[w*SEG + pos] = make_float4(f1.x, f1.y, f1.z, d1);
            }
            cnt += __popc(m1);
        }
    }
    if (lane == 0) s_cnt[w] = cnt;
    __syncthreads();

    int c0 = s_cnt[0], c1 = s_cnt[1], c2 = s_cnt[2], c3 = s_cnt[3];
    bool ovf = (c0 > SEG) | (c1 > SEG) | (c2 > SEG) | (c3 > SEG);
    int tot = c0 + c1 + c2 + c3;

    if (!ovf) {
        int base = (w > 0 ? c0 : 0) + (w > 1 ? c1 : 0) + (w > 2 ? c2 : 0);
        int mycnt = s_cnt[w];
        for (int i = lane; i < mycnt; i += 32) H[base + i] = Hseg[w*SEG + i];
        __syncthreads();
        if (w == 0) {
            double acc = 0.0;
            #pragma unroll
            for (int k = 0; k < 5; k++) {
                float r2 = L.r2[k];
                int ck = 0;
                for (int i = lane; i < tot; i += 32) ck += (H[i].w <= r2) ? 1 : 0;
                #pragma unroll
                for (int o = 16; o > 0; o >>= 1)
                    ck += __shfl_down_sync(0xffffffffu, ck, o);
                ck = __shfl_sync(0xffffffffu, ck, 0);
                float lsum = eval_level(H, tot, ck, r2, L.el[k], L.den[k], L.ns[k], lane);
                acc += L.w[k] * (double)lsum;
            }
            #pragma unroll
            for (int o = 16; o > 0; o >>= 1)
                acc += __shfl_down_sync(0xffffffffu, acc, o);
            if (lane == 0) atomicAdd(&g_acc[0], acc);
        }
    } else {
        if (w == 0) {
            double acc = 0.0;
            for (int k = 0; k < 5; k++) {
                float r2 = L.r2[k];
                int ns = L.ns[k];
                int c = 0;
                for (int it = 0; it < NPTS/32; it++) {
                    int j = it*32 + lane;
                    float4 f = P4[j];
                    float d = sqdist_f(f.x, f.y, f.z, qx, qy, qz);
                    bool hit = (d <= r2);
                    unsigned m = __ballot_sync(0xffffffffu, hit);
                    if (hit) {
                        int pos = c + __popc(m & ((1u << lane) - 1u));
                        if (pos < ns) H[pos] = make_float4(f.x, f.y, f.z, d);
                    }
                    c += __popc(m);
                }
                int stored = c < ns ? c : ns;
                float lsum = eval_level(H, stored, c, r2, L.el[k], L.den[k], ns, lane);
                acc += L.w[k] * (double)lsum;
            }
            #pragma unroll
            for (int o = 16; o > 0; o >>= 1)
                acc += __shfl_down_sync(0xffffffffu, acc, o);
            if (lane == 0) atomicAdd(&g_acc[0], acc);
        }
    }
}

__global__ void finalize_kernel(float* out) {
    out[0] = (float)g_acc[0];
    out[1] = (float)(g_acc[1] / (double)(NB * NPTS * 4));
}

// ============================  launch  ============================
#define FPS_SMEM (NPTS * sizeof(float4))   /* 128 KB */

static cudaStream_t g_s2;
static cudaEvent_t  g_ev0, g_ev1;
struct _StreamInit {
    _StreamInit() {
        cudaStreamCreateWithFlags(&g_s2, cudaStreamNonBlocking);
        cudaEventCreateWithFlags(&g_ev0, cudaEventDisableTiming);
        cudaEventCreateWithFlags(&g_ev1, cudaEventDisableTiming);
        cudaFuncSetAttribute(fps_kernel,
                             cudaFuncAttributeMaxDynamicSharedMemorySize,
                             (int)FPS_SMEM);
    }
};
static _StreamInit g_stream_init;

extern "C" void kernel_launch(void* const* d_in, const int* in_sizes, int n_in,
                              void* d_out, int out_size) {
    const float* pcd = (const float*)d_in[0];
    float* out = (float*)d_out;

    init_kernel<<<1, 1>>>();

    // fork: repulsion on side stream, concurrent with sort+FPS+uniform
    cudaEventRecord(g_ev0, 0);
    cudaStreamWaitEvent(g_s2, g_ev0, 0);
    {
        float r2     = (float)(0.07 * 0.07);
        float radius = (float)0.07;
        float hh     = (float)(0.03 * 0.03);
        repulsion_kernel<<<NB * (NPTS / RTILE), RTILE, 0, g_s2>>>(pcd, r2, radius, hh);
    }
    cudaEventRecord(g_ev1, g_s2);

    sort_kernel<<<NB, 1024>>>(pcd);
    fps_kernel<<<NB, 512, FPS_SMEM>>>(pcd);

    {
        static const double PS[5] = {0.004, 0.008, 0.01, 0.012, 0.016};
        ULevels L;
        for (int k = 0; k < 5; k++) {
            double p  = PS[k];
            int    ns = (int)(8192.0 * p);
            double r  = sqrt(p * 1.0);
            double disk = M_PI * 1.0 * p / (double)ns;
            double el   = sqrt(2.0 * disk / 1.732);
            L.r2[k]  = (float)(r * r);
            L.el[k]  = (float)el;
            L.den[k] = (float)(el + 1e-8);
            L.w[k]   = (p * 100.0) * (p * 100.0) / ((double)NG * (double)ns) / 5.0;
            L.ns[k]  = ns;
        }
        uniform_kernel<<<NG, 128>>>(L);
    }

    cudaStreamWaitEvent(0, g_ev1, 0);
    finalize_kernel<<<1, 1>>>(out);
}